// round 1
// baseline (speedup 1.0000x reference)
#include <cuda_runtime.h>
#include <cstdint>

// ---------------------------------------------------------------------------
// GCN layer:  out = D^-1/2 (adj+I) D^-1/2 @ ((x@W1^T+b1)@W2^T + b2)
// Folded as:  r = rsqrt(rowsum(adj)+1); h1 = x@W1^T+b1;
//             g = r ⊙ (h1@W2^T+b2);     out = diag(r) * (adj@g + g)
// All GEMMs: TF32 mma.sync m16n8k8, fp32 accumulate.
// ---------------------------------------------------------------------------

#define NN   8192
#define HID  256
#define OUTF 512

__device__ float g_h1[NN * HID];     // 8 MB scratch
__device__ float g_gbuf[NN * OUTF];  // 16 MB scratch
__device__ float g_r[NN];

__device__ __forceinline__ uint32_t f2tf(float f) {
    uint32_t u;
    asm("cvt.rna.tf32.f32 %0, %1;" : "=r"(u) : "f"(f));
    return u;
}

__device__ __forceinline__ void mma_tf32(float* c, const uint32_t* a,
                                         uint32_t b0, uint32_t b1) {
    asm volatile(
        "mma.sync.aligned.m16n8k8.row.col.f32.tf32.tf32.f32 "
        "{%0,%1,%2,%3},{%4,%5,%6,%7},{%8,%9},{%0,%1,%2,%3};"
        : "+f"(c[0]), "+f"(c[1]), "+f"(c[2]), "+f"(c[3])
        : "r"(a[0]), "r"(a[1]), "r"(a[2]), "r"(a[3]), "r"(b0), "r"(b1));
}

// ---------------------------------------------------------------------------
// rowsum + rsqrt:  r[i] = rsqrt(sum_j adj[i,j] + 1)
// ---------------------------------------------------------------------------
__global__ __launch_bounds__(256) void rowsum_kernel(const float* __restrict__ adj,
                                                     float* __restrict__ r, int ncols) {
    int row = blockIdx.x;
    const float4* p = reinterpret_cast<const float4*>(adj + (size_t)row * ncols);
    float s = 0.f;
    for (int i = threadIdx.x; i < ncols / 4; i += blockDim.x) {
        float4 v = p[i];
        s += (v.x + v.y) + (v.z + v.w);
    }
    // block reduce
    __shared__ float red[8];
    for (int o = 16; o > 0; o >>= 1) s += __shfl_down_sync(0xffffffffu, s, o);
    int lane = threadIdx.x & 31, warp = threadIdx.x >> 5;
    if (lane == 0) red[warp] = s;
    __syncthreads();
    if (warp == 0) {
        s = (lane < 8) ? red[lane] : 0.f;
        for (int o = 4; o > 0; o >>= 1) s += __shfl_down_sync(0xffffffffu, s, o);
        if (lane == 0) {
            float tot = s + 1.0f;
            r[row] = (tot > 0.f) ? rsqrtf(tot) : 0.f;
        }
    }
}

// ---------------------------------------------------------------------------
// Generic TF32 GEMM:  C[M,N] = A[M,K] @ B
//   BT=true : B is [N,K] row-major (k contiguous)  -> C = A @ B^T
//   BT=false: B is [K,N] row-major (n contiguous)  -> C = A @ B
// Epilogues:
//   EPI=0:  C = acc + bias[col]
//   EPI=1:  C = rvec[row] * (acc + bias[col])
//   EPI=2:  C = rvec[row] * (acc + gmat[row,col])
// Block tile 128x128, K-tile 32, 8 warps (4m x 2n), warp tile 32x64.
// ---------------------------------------------------------------------------
template <bool BT, int EPI>
__global__ __launch_bounds__(256) void gemm_tf32(
    const float* __restrict__ A, const float* __restrict__ B, float* __restrict__ C,
    int M, int N, int K,
    const float* __restrict__ bias, const float* __restrict__ rvec,
    const float* __restrict__ gmat) {

    __shared__ __align__(16) float As[128 * 36];   // [row][k], stride 36
    __shared__ __align__(16) float Bs[128 * 36];   // BT: [n][k] s36; !BT: [k][n] s132

    const int tid  = threadIdx.x;
    const int lane = tid & 31;
    const int warp = tid >> 5;
    const int wm = warp >> 1;          // 0..3
    const int wn = warp & 1;           // 0..1
    const int m0 = blockIdx.y * 128;
    const int n0 = blockIdx.x * 128;
    const int KT = K / 32;

    float acc[2][8][4];
#pragma unroll
    for (int mi = 0; mi < 2; mi++)
#pragma unroll
        for (int nj = 0; nj < 8; nj++)
#pragma unroll
            for (int q = 0; q < 4; q++) acc[mi][nj][q] = 0.f;

    float4 pa[4], pb[4];

    auto loadA = [&](int kt, float4* p) {
#pragma unroll
        for (int i = 0; i < 4; i++) {
            int idx = tid + i * 256;
            int row = idx >> 3;
            int kc  = (idx & 7) << 2;
            p[i] = *reinterpret_cast<const float4*>(
                &A[(size_t)(m0 + row) * K + kt * 32 + kc]);
        }
    };
    auto storeA = [&](const float4* p) {
#pragma unroll
        for (int i = 0; i < 4; i++) {
            int idx = tid + i * 256;
            int row = idx >> 3;
            int kc  = (idx & 7) << 2;
            uint4 t = make_uint4(f2tf(p[i].x), f2tf(p[i].y), f2tf(p[i].z), f2tf(p[i].w));
            *reinterpret_cast<uint4*>(&As[row * 36 + kc]) = t;
        }
    };
    auto loadB = [&](int kt, float4* p) {
#pragma unroll
        for (int i = 0; i < 4; i++) {
            int idx = tid + i * 256;
            if (BT) {
                int row = idx >> 3;
                int kc  = (idx & 7) << 2;
                p[i] = *reinterpret_cast<const float4*>(
                    &B[(size_t)(n0 + row) * K + kt * 32 + kc]);
            } else {
                int krow = idx >> 5;
                int nc   = (idx & 31) << 2;
                p[i] = *reinterpret_cast<const float4*>(
                    &B[(size_t)(kt * 32 + krow) * N + n0 + nc]);
            }
        }
    };
    auto storeB = [&](const float4* p) {
#pragma unroll
        for (int i = 0; i < 4; i++) {
            int idx = tid + i * 256;
            uint4 t = make_uint4(f2tf(p[i].x), f2tf(p[i].y), f2tf(p[i].z), f2tf(p[i].w));
            if (BT) {
                int row = idx >> 3;
                int kc  = (idx & 7) << 2;
                *reinterpret_cast<uint4*>(&Bs[row * 36 + kc]) = t;
            } else {
                int krow = idx >> 5;
                int nc   = (idx & 31) << 2;
                *reinterpret_cast<uint4*>(&Bs[krow * 132 + nc]) = t;
            }
        }
    };

    loadA(0, pa); loadB(0, pb);
    storeA(pa);   storeB(pb);
    __syncthreads();

    for (int kt = 0; kt < KT; kt++) {
        if (kt + 1 < KT) { loadA(kt + 1, pa); loadB(kt + 1, pb); }

#pragma unroll
        for (int kk = 0; kk < 4; kk++) {
            uint32_t afr[2][4];
#pragma unroll
            for (int mi = 0; mi < 2; mi++) {
                int r0 = wm * 32 + mi * 16 + (lane >> 2);
                int kb = kk * 8 + (lane & 3);
                afr[mi][0] = __float_as_uint(As[r0 * 36 + kb]);
                afr[mi][1] = __float_as_uint(As[(r0 + 8) * 36 + kb]);
                afr[mi][2] = __float_as_uint(As[r0 * 36 + kb + 4]);
                afr[mi][3] = __float_as_uint(As[(r0 + 8) * 36 + kb + 4]);
            }
#pragma unroll
            for (int nj = 0; nj < 8; nj++) {
                int nn = wn * 64 + nj * 8 + (lane >> 2);
                int k0 = kk * 8 + (lane & 3);
                uint32_t b0, b1;
                if (BT) {
                    b0 = __float_as_uint(Bs[nn * 36 + k0]);
                    b1 = __float_as_uint(Bs[nn * 36 + k0 + 4]);
                } else {
                    b0 = __float_as_uint(Bs[k0 * 132 + nn]);
                    b1 = __float_as_uint(Bs[(k0 + 4) * 132 + nn]);
                }
                mma_tf32(acc[0][nj], afr[0], b0, b1);
                mma_tf32(acc[1][nj], afr[1], b0, b1);
            }
        }
        __syncthreads();
        if (kt + 1 < KT) {
            storeA(pa); storeB(pb);
            __syncthreads();
        }
    }

    // epilogue
    const int lr  = lane >> 2;
    const int lc2 = (lane & 3) * 2;
#pragma unroll
    for (int mi = 0; mi < 2; mi++) {
#pragma unroll
        for (int nj = 0; nj < 8; nj++) {
            int row = m0 + wm * 32 + mi * 16 + lr;
            int col = n0 + wn * 64 + nj * 8 + lc2;
            const float* cc = acc[mi][nj];
#pragma unroll
            for (int half = 0; half < 2; half++) {
                int rr_row = row + half * 8;
                float v0 = cc[half * 2 + 0];
                float v1 = cc[half * 2 + 1];
                float2 o;
                if (EPI == 0) {
                    o.x = v0 + bias[col];
                    o.y = v1 + bias[col + 1];
                } else if (EPI == 1) {
                    float rv = rvec[rr_row];
                    o.x = rv * (v0 + bias[col]);
                    o.y = rv * (v1 + bias[col + 1]);
                } else {
                    float rv = rvec[rr_row];
                    float2 gg = *reinterpret_cast<const float2*>(
                        &gmat[(size_t)rr_row * N + col]);
                    o.x = rv * (v0 + gg.x);
                    o.y = rv * (v1 + gg.y);
                }
                *reinterpret_cast<float2*>(&C[(size_t)rr_row * N + col]) = o;
            }
        }
    }
}

// ---------------------------------------------------------------------------
extern "C" void kernel_launch(void* const* d_in, const int* in_sizes, int n_in,
                              void* d_out, int out_size) {
    const float* x   = (const float*)d_in[0];
    const float* adj = (const float*)d_in[1];
    const float* W1  = (const float*)d_in[2];
    const float* b1  = (const float*)d_in[3];
    const float* W2  = (const float*)d_in[4];
    const float* b2  = (const float*)d_in[5];
    float* out = (float*)d_out;

    float *h1p, *gp, *rp;
    cudaGetSymbolAddress((void**)&h1p, g_h1);
    cudaGetSymbolAddress((void**)&gp, g_gbuf);
    cudaGetSymbolAddress((void**)&rp, g_r);

    // r = rsqrt(rowsum(adj)+1)
    rowsum_kernel<<<NN, 256>>>(adj, rp, NN);
    // h1 = x @ W1^T + b1            [8192,256]
    gemm_tf32<true, 0><<<dim3(HID / 128, NN / 128), 256>>>(
        x, W1, h1p, NN, HID, 512, b1, nullptr, nullptr);
    // g = r ⊙ (h1 @ W2^T + b2)      [8192,512]
    gemm_tf32<true, 1><<<dim3(OUTF / 128, NN / 128), 256>>>(
        h1p, W2, gp, NN, OUTF, HID, b2, rp, nullptr);
    // out = diag(r) * (adj @ g + g) [8192,512]
    gemm_tf32<false, 2><<<dim3(OUTF / 128, NN / 128), 256>>>(
        adj, gp, out, NN, OUTF, NN, nullptr, rp, gp);
}

// round 3
// speedup vs baseline: 1.3043x; 1.3043x over previous
#include <cuda_runtime.h>
#include <cstdint>

// ---------------------------------------------------------------------------
// GCN layer:  out = D^-1/2 (adj+I) D^-1/2 @ ((x@W1^T+b1)@W2^T + b2)
// Folded:  r = rsqrt(rowsum(adj)+1); h1 = x@W1^T+b1;
//          g = r ⊙ (h1@W2^T+b2);     out = diag(r) * (adj@g + g)
// All GEMMs: TF32 mma.sync m16n8k8 (tcgen05 PTX is rejected: harness PTX
// target is compute_103 without the 'a' suffix).
// GEMM3 uses fragment-paired smem layouts (all LDS.64), B pre-packed into
// fragment order by GEMM2's epilogue and streamed via cp.async.
// ---------------------------------------------------------------------------

#define NN   8192
#define HID  256
#define OUTF 512

__device__ float g_h1[NN * HID];        // 8 MB
__device__ float g_gbuf[NN * OUTF];     // 16 MB  g row-major (unrounded, for +g)
__device__ float g_gBp[1024 * OUTF * 8];// 16 MB  B fragment-packed (tf32-rounded)
__device__ float g_r[NN];

__device__ __forceinline__ uint32_t f2tf(float f) {
    uint32_t u;
    asm("cvt.rna.tf32.f32 %0, %1;" : "=r"(u) : "f"(f));
    return u;
}

__device__ __forceinline__ uint32_t smem_u32(const void* p) {
    uint32_t a;
    asm("{ .reg .u64 t; cvta.to.shared.u64 t, %1; cvt.u32.u64 %0, t; }"
        : "=r"(a) : "l"(p));
    return a;
}

__device__ __forceinline__ void mma_tf32(float* c, const uint32_t* a,
                                         uint32_t b0, uint32_t b1) {
    asm volatile(
        "mma.sync.aligned.m16n8k8.row.col.f32.tf32.tf32.f32 "
        "{%0,%1,%2,%3},{%4,%5,%6,%7},{%8,%9},{%0,%1,%2,%3};"
        : "+f"(c[0]), "+f"(c[1]), "+f"(c[2]), "+f"(c[3])
        : "r"(a[0]), "r"(a[1]), "r"(a[2]), "r"(a[3]), "r"(b0), "r"(b1));
}

#define CP_ASYNC16(dst, src) \
    asm volatile("cp.async.cg.shared.global [%0], [%1], 16;" \
                 :: "r"(dst), "l"(src) : "memory")
#define CP_COMMIT() asm volatile("cp.async.commit_group;" ::: "memory")
#define CP_WAIT0()  asm volatile("cp.async.wait_group 0;" ::: "memory")

// ---------------------------------------------------------------------------
// rowsum + rsqrt:  r[i] = rsqrt(sum_j adj[i,j] + 1)
// ---------------------------------------------------------------------------
__global__ __launch_bounds__(256) void rowsum_kernel(const float* __restrict__ adj,
                                                     float* __restrict__ r, int ncols) {
    int row = blockIdx.x;
    const float4* p = reinterpret_cast<const float4*>(adj + (size_t)row * ncols);
    float s = 0.f;
    for (int i = threadIdx.x; i < ncols / 4; i += blockDim.x) {
        float4 v = p[i];
        s += (v.x + v.y) + (v.z + v.w);
    }
    __shared__ float red[8];
    for (int o = 16; o > 0; o >>= 1) s += __shfl_down_sync(0xffffffffu, s, o);
    int lane = threadIdx.x & 31, warp = threadIdx.x >> 5;
    if (lane == 0) red[warp] = s;
    __syncthreads();
    if (warp == 0) {
        s = (lane < 8) ? red[lane] : 0.f;
        for (int o = 4; o > 0; o >>= 1) s += __shfl_down_sync(0xffffffffu, s, o);
        if (lane == 0) {
            float tot = s + 1.0f;
            r[row] = (tot > 0.f) ? rsqrtf(tot) : 0.f;
        }
    }
}

// ---------------------------------------------------------------------------
// Small dense GEMMs:  C = A @ B^T  (B is [N,K] row-major)
// EPI=0: C = acc + bias[col]
// EPI=1: C = rvec[row]*(acc+bias[col]); also scatter tf32(C) into gBp
//        fragment-packed for GEMM3's B operand.
// ---------------------------------------------------------------------------
template <int EPI>
__global__ __launch_bounds__(256) void gemm_tf32(
    const float* __restrict__ A, const float* __restrict__ B, float* __restrict__ C,
    int M, int N, int K,
    const float* __restrict__ bias, const float* __restrict__ rvec,
    float* __restrict__ gBp) {

    __shared__ __align__(16) float As[128 * 36];
    __shared__ __align__(16) float Bs[128 * 36];

    const int tid  = threadIdx.x;
    const int lane = tid & 31;
    const int warp = tid >> 5;
    const int wm = warp >> 1;
    const int wn = warp & 1;
    const int m0 = blockIdx.y * 128;
    const int n0 = blockIdx.x * 128;
    const int KT = K / 32;

    float acc[2][8][4];
#pragma unroll
    for (int mi = 0; mi < 2; mi++)
#pragma unroll
        for (int nj = 0; nj < 8; nj++)
#pragma unroll
            for (int q = 0; q < 4; q++) acc[mi][nj][q] = 0.f;

    float4 pa[4], pb[4];

    auto loadA = [&](int kt, float4* p) {
#pragma unroll
        for (int i = 0; i < 4; i++) {
            int idx = tid + i * 256;
            int row = idx >> 3;
            int kc  = (idx & 7) << 2;
            p[i] = *reinterpret_cast<const float4*>(
                &A[(size_t)(m0 + row) * K + kt * 32 + kc]);
        }
    };
    auto storeA = [&](const float4* p) {
#pragma unroll
        for (int i = 0; i < 4; i++) {
            int idx = tid + i * 256;
            int row = idx >> 3;
            int kc  = (idx & 7) << 2;
            uint4 t = make_uint4(f2tf(p[i].x), f2tf(p[i].y), f2tf(p[i].z), f2tf(p[i].w));
            *reinterpret_cast<uint4*>(&As[row * 36 + kc]) = t;
        }
    };
    auto loadB = [&](int kt, float4* p) {
#pragma unroll
        for (int i = 0; i < 4; i++) {
            int idx = tid + i * 256;
            int row = idx >> 3;
            int kc  = (idx & 7) << 2;
            p[i] = *reinterpret_cast<const float4*>(
                &B[(size_t)(n0 + row) * K + kt * 32 + kc]);
        }
    };
    auto storeB = [&](const float4* p) {
#pragma unroll
        for (int i = 0; i < 4; i++) {
            int idx = tid + i * 256;
            int row = idx >> 3;
            int kc  = (idx & 7) << 2;
            uint4 t = make_uint4(f2tf(p[i].x), f2tf(p[i].y), f2tf(p[i].z), f2tf(p[i].w));
            *reinterpret_cast<uint4*>(&Bs[row * 36 + kc]) = t;
        }
    };

    loadA(0, pa); loadB(0, pb);
    storeA(pa);   storeB(pb);
    __syncthreads();

    for (int kt = 0; kt < KT; kt++) {
        if (kt + 1 < KT) { loadA(kt + 1, pa); loadB(kt + 1, pb); }

#pragma unroll
        for (int kk = 0; kk < 4; kk++) {
            uint32_t afr[2][4];
#pragma unroll
            for (int mi = 0; mi < 2; mi++) {
                int r0 = wm * 32 + mi * 16 + (lane >> 2);
                int kb = kk * 8 + (lane & 3);
                afr[mi][0] = __float_as_uint(As[r0 * 36 + kb]);
                afr[mi][1] = __float_as_uint(As[(r0 + 8) * 36 + kb]);
                afr[mi][2] = __float_as_uint(As[r0 * 36 + kb + 4]);
                afr[mi][3] = __float_as_uint(As[(r0 + 8) * 36 + kb + 4]);
            }
#pragma unroll
            for (int nj = 0; nj < 8; nj++) {
                int nn = wn * 64 + nj * 8 + (lane >> 2);
                int k0 = kk * 8 + (lane & 3);
                uint32_t b0 = __float_as_uint(Bs[nn * 36 + k0]);
                uint32_t b1 = __float_as_uint(Bs[nn * 36 + k0 + 4]);
                mma_tf32(acc[0][nj], afr[0], b0, b1);
                mma_tf32(acc[1][nj], afr[1], b0, b1);
            }
        }
        __syncthreads();
        if (kt + 1 < KT) {
            storeA(pa); storeB(pb);
            __syncthreads();
        }
    }

    const int lr  = lane >> 2;
    const int lc2 = (lane & 3) * 2;
#pragma unroll
    for (int mi = 0; mi < 2; mi++) {
#pragma unroll
        for (int nj = 0; nj < 8; nj++) {
            int row = m0 + wm * 32 + mi * 16 + lr;
            int col = n0 + wn * 64 + nj * 8 + lc2;
            const float* cc = acc[mi][nj];
#pragma unroll
            for (int half = 0; half < 2; half++) {
                int rr = row + half * 8;
                float v0 = cc[half * 2 + 0];
                float v1 = cc[half * 2 + 1];
                float2 o;
                if (EPI == 0) {
                    o.x = v0 + bias[col];
                    o.y = v1 + bias[col + 1];
                } else {
                    float rv = rvec[rr];
                    o.x = rv * (v0 + bias[col]);
                    o.y = rv * (v1 + bias[col + 1]);
                    // scatter tf32-rounded values into GEMM3's fragment-packed B:
                    // gBp[((k>>3)*512 + n)*8 + (k&3)*2 + ((k>>2)&1)],  k=rr, n=col
                    size_t base = ((size_t)(rr >> 3) * OUTF + col) * 8
                                + (size_t)(rr & 3) * 2 + ((rr >> 2) & 1);
                    gBp[base]     = __uint_as_float(f2tf(o.x));
                    gBp[base + 8] = __uint_as_float(f2tf(o.y));
                }
                *reinterpret_cast<float2*>(&C[(size_t)rr * N + col]) = o;
            }
        }
    }
}

// ---------------------------------------------------------------------------
// GEMM3: out = diag(r) * (adj @ g + g)     [8192 x 512] , K = 8192
// CTA tile 128m x 256n, K-tile 32. 8 warps, warp tile 32m x 128n.
// A: LDG -> cvt.rna.tf32 -> paired STS.64 (pairs {row,row+8}, XOR swizzle).
// B: cp.async straight copy of fragment-packed gBp (pairs {k,k+4}).
// All consumer operand fetches are conflict-free LDS.64.
// ---------------------------------------------------------------------------
#define G3_ASZ (128 * 32)            // floats per A buffer (16 KB)
#define G3_BSZ (256 * 32)            // floats per B buffer (32 KB)
#define G3_SMEM ((2 * G3_ASZ + 2 * G3_BSZ) * 4)   // 96 KB

__global__ __launch_bounds__(256, 1) void gemm3_mma(
    const float* __restrict__ adj, const float* __restrict__ gBp,
    const float* __restrict__ g, const float* __restrict__ rvec,
    float* __restrict__ out) {

    extern __shared__ __align__(16) float smem[];
    float* As = smem;                  // 2 x G3_ASZ
    float* Bs = smem + 2 * G3_ASZ;     // 2 x G3_BSZ

    const int tid  = threadIdx.x;
    const int lane = tid & 31;
    const int warp = tid >> 5;
    const int wm = warp >> 1;          // 0..3
    const int wn = warp & 1;           // 0..1
    const int m0 = blockIdx.y * 128;
    const int n0 = blockIdx.x * 256;

    // A producer geometry (per thread): 2 row-pairs x 4 consecutive k
    const int prl = tid >> 3;          // 0..31
    const int gq  = prl & 7;           // g of pair (0..7)
    const int kc  = (tid & 7) << 2;    // k offset 0,4,...,28
    const int swc = tid & 7;           // (k>>2)&7 for all 4 q  (kc/4)
    // rows for i=0: blk16 = prl>>3 ; i=1: blk16+4
    float4 va[2][2];

    auto ldA = [&](int kt) {
        const size_t kbase = (size_t)kt * 32 + kc;
#pragma unroll
        for (int i = 0; i < 2; i++) {
            int blk = (prl >> 3) + i * 4;
            int r0 = blk * 16 + gq;
            va[i][0] = *reinterpret_cast<const float4*>(
                adj + (size_t)(m0 + r0) * NN + kbase);
            va[i][1] = *reinterpret_cast<const float4*>(
                adj + (size_t)(m0 + r0 + 8) * NN + kbase);
        }
    };
    auto stA = [&](int buf) {
        float* dst = As + buf * G3_ASZ;
        const int gx = (gq ^ swc) << 1;
#pragma unroll
        for (int i = 0; i < 2; i++) {
            int blk = (prl >> 3) + i * 4;
            const float* v0 = &va[i][0].x;
            const float* v1 = &va[i][1].x;
#pragma unroll
            for (int q = 0; q < 4; q++) {
                int off = ((blk * 32 + kc + q) << 4) + gx;
                dst[off]     = __uint_as_float(f2tf(v0[q]));
                dst[off + 1] = __uint_as_float(f2tf(v1[q]));
            }
        }
    };
    auto cpB = [&](int kt, int buf) {
        // gBp rows (k>>3) = kt*4 + j ; each row 512*8 floats = 1024 float4
        const float4* src4 = reinterpret_cast<const float4*>(gBp);
        uint32_t dst = smem_u32(Bs + buf * G3_BSZ);
#pragma unroll
        for (int i = 0; i < 8; i++) {
            int f = i * 256 + tid;         // 0..2047 float4 slots
            int j   = f >> 9;              // 0..3
            int off = f & 511;
            const float4* s = src4 + ((size_t)(kt * 4 + j) * 1024 + n0 * 2 + off);
            CP_ASYNC16(dst + (uint32_t)((j * 512 + off) * 16), s);
        }
    };

    float acc[2][16][4];
#pragma unroll
    for (int mi = 0; mi < 2; mi++)
#pragma unroll
        for (int nj = 0; nj < 16; nj++)
#pragma unroll
            for (int q = 0; q < 4; q++) acc[mi][nj][q] = 0.f;

    // prologue
    ldA(0);
    cpB(0, 0);
    CP_COMMIT();
    stA(0);
    CP_WAIT0();
    __syncthreads();

    const int g7 = lane >> 2;          // 0..7
    const int t4 = lane & 3;           // 0..3

    for (int kt = 0; kt < NN / 32; kt++) {
        const int buf = kt & 1;
        const bool more = (kt + 1 < NN / 32);
        if (more) {
            ldA(kt + 1);
            cpB(kt + 1, buf ^ 1);
            CP_COMMIT();
        }

        const float* Ab = As + buf * G3_ASZ;
        const float* Bb = Bs + buf * G3_BSZ;

#pragma unroll
        for (int kk = 0; kk < 4; kk++) {
            const int c0 = (kk * 2) & 7;
            const int c1 = (kk * 2 + 1) & 7;
            uint32_t afr[2][4];
#pragma unroll
            for (int mi = 0; mi < 2; mi++) {
                int blk = wm * 2 + mi;
                const float2 a01 = *reinterpret_cast<const float2*>(
                    Ab + ((blk * 32 + kk * 8 + t4) << 4) + ((g7 ^ c0) << 1));
                const float2 a23 = *reinterpret_cast<const float2*>(
                    Ab + ((blk * 32 + kk * 8 + 4 + t4) << 4) + ((g7 ^ c1) << 1));
                afr[mi][0] = __float_as_uint(a01.x);
                afr[mi][1] = __float_as_uint(a01.y);
                afr[mi][2] = __float_as_uint(a23.x);
                afr[mi][3] = __float_as_uint(a23.y);
            }
#pragma unroll
            for (int nj = 0; nj < 16; nj++) {
                int n = wn * 128 + nj * 8 + g7;
                const float2 b01 = *reinterpret_cast<const float2*>(
                    Bb + ((kk * 256 + n) << 3) + (t4 << 1));
                uint32_t b0 = __float_as_uint(b01.x);
                uint32_t b1 = __float_as_uint(b01.y);
                mma_tf32(acc[0][nj], afr[0], b0, b1);
                mma_tf32(acc[1][nj], afr[1], b0, b1);
            }
        }

        if (more) stA(buf ^ 1);
        CP_WAIT0();
        __syncthreads();
    }

    // epilogue: out = r * (acc + g)
#pragma unroll
    for (int mi = 0; mi < 2; mi++) {
#pragma unroll
        for (int h = 0; h < 2; h++) {
            int row = m0 + wm * 32 + mi * 16 + g7 + h * 8;
            float rv = rvec[row];
            const float* gp = g + (size_t)row * OUTF;
            float* op = out + (size_t)row * OUTF;
#pragma unroll
            for (int nj = 0; nj < 16; nj++) {
                int col = n0 + wn * 128 + nj * 8 + t4 * 2;
                float2 gg = *reinterpret_cast<const float2*>(gp + col);
                float2 o;
                o.x = rv * (acc[mi][nj][h * 2 + 0] + gg.x);
                o.y = rv * (acc[mi][nj][h * 2 + 1] + gg.y);
                *reinterpret_cast<float2*>(op + col) = o;
            }
        }
    }
}

// ---------------------------------------------------------------------------
extern "C" void kernel_launch(void* const* d_in, const int* in_sizes, int n_in,
                              void* d_out, int out_size) {
    const float* x   = (const float*)d_in[0];
    const float* adj = (const float*)d_in[1];
    const float* W1  = (const float*)d_in[2];
    const float* b1  = (const float*)d_in[3];
    const float* W2  = (const float*)d_in[4];
    const float* b2  = (const float*)d_in[5];
    float* out = (float*)d_out;

    float *h1p, *gp, *gBpp, *rp;
    cudaGetSymbolAddress((void**)&h1p, g_h1);
    cudaGetSymbolAddress((void**)&gp, g_gbuf);
    cudaGetSymbolAddress((void**)&gBpp, g_gBp);
    cudaGetSymbolAddress((void**)&rp, g_r);

    cudaFuncSetAttribute(gemm3_mma, cudaFuncAttributeMaxDynamicSharedMemorySize,
                         G3_SMEM);

    // r = rsqrt(rowsum(adj)+1)
    rowsum_kernel<<<NN, 256>>>(adj, rp, NN);
    // h1 = x @ W1^T + b1                        [8192,256]
    gemm_tf32<0><<<dim3(HID / 128, NN / 128), 256>>>(
        x, W1, h1p, NN, HID, 512, b1, nullptr, nullptr);
    // g = r ⊙ (h1 @ W2^T + b2); pack tf32(g) into gBp  [8192,512]
    gemm_tf32<1><<<dim3(OUTF / 128, NN / 128), 256>>>(
        h1p, W2, gp, NN, OUTF, HID, b2, rp, gBpp);
    // out = diag(r) * (adj @ g + g)             [8192,512]
    gemm3_mma<<<dim3(OUTF / 256, NN / 128), 256, G3_SMEM>>>(
        adj, gBpp, gp, rp, out);
}

// round 4
// speedup vs baseline: 1.5797x; 1.2112x over previous
#include <cuda_runtime.h>
#include <cstdint>

// ---------------------------------------------------------------------------
// GCN layer:  out = D^-1/2 (adj+I) D^-1/2 @ ((x@W1^T+b1)@W2^T + b2)
// Folded:  r = rsqrt(rowsum(adj)+1); h1 = x@W1^T+b1;
//          g = r ⊙ (h1@W2^T+b2);     out = diag(r) * (adj@g + g)
// GEMM1/2: tf32 mma.sync. GEMM3: fp16 mma.sync m16n8k16 (same 11-bit
// effective mantissa as tf32 for these small-range operands, 2x rate,
// half the smem operand bytes). B pre-packed to fp16 fragments in gmem.
// ---------------------------------------------------------------------------

#define NN   8192
#define HID  256
#define OUTF 512

__device__ float g_h1[NN * HID];       // 8 MB
__device__ float g_gbuf[NN * OUTF];    // 16 MB  g (fp32, row-major)
__device__ uint4 g_Bp[512 * 512 * 2];  // 8 MB   g fragment-packed fp16
__device__ float g_r[NN];

__device__ __forceinline__ uint32_t f2tf(float f) {
    uint32_t u;
    asm("cvt.rna.tf32.f32 %0, %1;" : "=r"(u) : "f"(f));
    return u;
}
// pack {lo, hi} floats into f16x2 (lo in bits[15:0])
__device__ __forceinline__ uint32_t pk16(float hi, float lo) {
    uint32_t u;
    asm("cvt.rn.f16x2.f32 %0, %1, %2;" : "=r"(u) : "f"(hi), "f"(lo));
    return u;
}
__device__ __forceinline__ uint32_t smem_u32(const void* p) {
    uint32_t a;
    asm("{ .reg .u64 t; cvta.to.shared.u64 t, %1; cvt.u32.u64 %0, t; }"
        : "=r"(a) : "l"(p));
    return a;
}
__device__ __forceinline__ void mma_tf32(float* c, const uint32_t* a,
                                         uint32_t b0, uint32_t b1) {
    asm volatile(
        "mma.sync.aligned.m16n8k8.row.col.f32.tf32.tf32.f32 "
        "{%0,%1,%2,%3},{%4,%5,%6,%7},{%8,%9},{%0,%1,%2,%3};"
        : "+f"(c[0]), "+f"(c[1]), "+f"(c[2]), "+f"(c[3])
        : "r"(a[0]), "r"(a[1]), "r"(a[2]), "r"(a[3]), "r"(b0), "r"(b1));
}
__device__ __forceinline__ void mma_fp16(float* c, const uint32_t* a,
                                         const uint32_t* b) {
    asm volatile(
        "mma.sync.aligned.m16n8k16.row.col.f32.f16.f16.f32 "
        "{%0,%1,%2,%3},{%4,%5,%6,%7},{%8,%9},{%0,%1,%2,%3};"
        : "+f"(c[0]), "+f"(c[1]), "+f"(c[2]), "+f"(c[3])
        : "r"(a[0]), "r"(a[1]), "r"(a[2]), "r"(a[3]), "r"(b[0]), "r"(b[1]));
}

#define CP_ASYNC16(dst, src) \
    asm volatile("cp.async.cg.shared.global [%0], [%1], 16;" \
                 :: "r"(dst), "l"(src) : "memory")
#define CP_COMMIT() asm volatile("cp.async.commit_group;" ::: "memory")
#define CP_WAIT0()  asm volatile("cp.async.wait_group 0;" ::: "memory")

// ---------------------------------------------------------------------------
// rowsum + rsqrt
// ---------------------------------------------------------------------------
__global__ __launch_bounds__(256) void rowsum_kernel(const float* __restrict__ adj,
                                                     float* __restrict__ r, int ncols) {
    int row = blockIdx.x;
    const float4* p = reinterpret_cast<const float4*>(adj + (size_t)row * ncols);
    float s = 0.f;
    for (int i = threadIdx.x; i < ncols / 4; i += blockDim.x) {
        float4 v = p[i];
        s += (v.x + v.y) + (v.z + v.w);
    }
    __shared__ float red[8];
    for (int o = 16; o > 0; o >>= 1) s += __shfl_down_sync(0xffffffffu, s, o);
    int lane = threadIdx.x & 31, warp = threadIdx.x >> 5;
    if (lane == 0) red[warp] = s;
    __syncthreads();
    if (warp == 0) {
        s = (lane < 8) ? red[lane] : 0.f;
        for (int o = 4; o > 0; o >>= 1) s += __shfl_down_sync(0xffffffffu, s, o);
        if (lane == 0) {
            float tot = s + 1.0f;
            r[row] = (tot > 0.f) ? rsqrtf(tot) : 0.f;
        }
    }
}

// ---------------------------------------------------------------------------
// Small dense GEMMs (tf32):  C = A @ B^T
// EPI=0: C = acc + bias[col];  EPI=1: C = rvec[row]*(acc+bias[col])
// ---------------------------------------------------------------------------
template <int EPI>
__global__ __launch_bounds__(256) void gemm_tf32(
    const float* __restrict__ A, const float* __restrict__ B, float* __restrict__ C,
    int M, int N, int K,
    const float* __restrict__ bias, const float* __restrict__ rvec) {

    __shared__ __align__(16) float As[128 * 36];
    __shared__ __align__(16) float Bs[128 * 36];

    const int tid  = threadIdx.x;
    const int lane = tid & 31;
    const int warp = tid >> 5;
    const int wm = warp >> 1;
    const int wn = warp & 1;
    const int m0 = blockIdx.y * 128;
    const int n0 = blockIdx.x * 128;
    const int KT = K / 32;

    float acc[2][8][4];
#pragma unroll
    for (int mi = 0; mi < 2; mi++)
#pragma unroll
        for (int nj = 0; nj < 8; nj++)
#pragma unroll
            for (int q = 0; q < 4; q++) acc[mi][nj][q] = 0.f;

    float4 pa[4], pb[4];

    auto loadA = [&](int kt, float4* p) {
#pragma unroll
        for (int i = 0; i < 4; i++) {
            int idx = tid + i * 256;
            int row = idx >> 3;
            int kc  = (idx & 7) << 2;
            p[i] = *reinterpret_cast<const float4*>(
                &A[(size_t)(m0 + row) * K + kt * 32 + kc]);
        }
    };
    auto storeA = [&](const float4* p) {
#pragma unroll
        for (int i = 0; i < 4; i++) {
            int idx = tid + i * 256;
            int row = idx >> 3;
            int kc  = (idx & 7) << 2;
            uint4 t = make_uint4(f2tf(p[i].x), f2tf(p[i].y), f2tf(p[i].z), f2tf(p[i].w));
            *reinterpret_cast<uint4*>(&As[row * 36 + kc]) = t;
        }
    };
    auto loadB = [&](int kt, float4* p) {
#pragma unroll
        for (int i = 0; i < 4; i++) {
            int idx = tid + i * 256;
            int row = idx >> 3;
            int kc  = (idx & 7) << 2;
            p[i] = *reinterpret_cast<const float4*>(
                &B[(size_t)(n0 + row) * K + kt * 32 + kc]);
        }
    };
    auto storeB = [&](const float4* p) {
#pragma unroll
        for (int i = 0; i < 4; i++) {
            int idx = tid + i * 256;
            int row = idx >> 3;
            int kc  = (idx & 7) << 2;
            uint4 t = make_uint4(f2tf(p[i].x), f2tf(p[i].y), f2tf(p[i].z), f2tf(p[i].w));
            *reinterpret_cast<uint4*>(&Bs[row * 36 + kc]) = t;
        }
    };

    loadA(0, pa); loadB(0, pb);
    storeA(pa);   storeB(pb);
    __syncthreads();

    for (int kt = 0; kt < KT; kt++) {
        if (kt + 1 < KT) { loadA(kt + 1, pa); loadB(kt + 1, pb); }

#pragma unroll
        for (int kk = 0; kk < 4; kk++) {
            uint32_t afr[2][4];
#pragma unroll
            for (int mi = 0; mi < 2; mi++) {
                int r0 = wm * 32 + mi * 16 + (lane >> 2);
                int kb = kk * 8 + (lane & 3);
                afr[mi][0] = __float_as_uint(As[r0 * 36 + kb]);
                afr[mi][1] = __float_as_uint(As[(r0 + 8) * 36 + kb]);
                afr[mi][2] = __float_as_uint(As[r0 * 36 + kb + 4]);
                afr[mi][3] = __float_as_uint(As[(r0 + 8) * 36 + kb + 4]);
            }
#pragma unroll
            for (int nj = 0; nj < 8; nj++) {
                int nn = wn * 64 + nj * 8 + (lane >> 2);
                int k0 = kk * 8 + (lane & 3);
                uint32_t b0 = __float_as_uint(Bs[nn * 36 + k0]);
                uint32_t b1 = __float_as_uint(Bs[nn * 36 + k0 + 4]);
                mma_tf32(acc[0][nj], afr[0], b0, b1);
                mma_tf32(acc[1][nj], afr[1], b0, b1);
            }
        }
        __syncthreads();
        if (kt + 1 < KT) {
            storeA(pa); storeB(pb);
            __syncthreads();
        }
    }

    const int lr  = lane >> 2;
    const int lc2 = (lane & 3) * 2;
#pragma unroll
    for (int mi = 0; mi < 2; mi++) {
#pragma unroll
        for (int nj = 0; nj < 8; nj++) {
            int row = m0 + wm * 32 + mi * 16 + lr;
            int col = n0 + wn * 64 + nj * 8 + lc2;
            const float* cc = acc[mi][nj];
#pragma unroll
            for (int half = 0; half < 2; half++) {
                int rr = row + half * 8;
                float v0 = cc[half * 2 + 0];
                float v1 = cc[half * 2 + 1];
                float2 o;
                if (EPI == 0) {
                    o.x = v0 + bias[col];
                    o.y = v1 + bias[col + 1];
                } else {
                    float rv = rvec[rr];
                    o.x = rv * (v0 + bias[col]);
                    o.y = rv * (v1 + bias[col + 1]);
                }
                *reinterpret_cast<float2*>(&C[(size_t)rr * N + col]) = o;
            }
        }
    }
}

// ---------------------------------------------------------------------------
// Pack g (fp32 [8192,512]) into fragment-packed fp16 for m16n8k16 B operand.
// Unit (K16, n, t4) = 8 bytes: word0 = {g[K16*16+2t4][n], g[..+2t4+1][n]},
//                             word1 = {.. +2t4+8, .. +2t4+9}.
// Layout: byte = ((K16*512 + n)*4 + t4)*8  -> thread writes 32 contiguous B.
// ---------------------------------------------------------------------------
__global__ __launch_bounds__(128) void pack_fp16(const float* __restrict__ g,
                                                 uint4* __restrict__ Bp) {
    const int K16 = blockIdx.x;
    const int n   = blockIdx.y * 128 + threadIdx.x;
    float v[16];
#pragma unroll
    for (int kin = 0; kin < 16; kin++)
        v[kin] = g[(size_t)(K16 * 16 + kin) * OUTF + n];
    uint4 lo, hi;
    lo.x = pk16(v[1], v[0]);   lo.y = pk16(v[9], v[8]);
    lo.z = pk16(v[3], v[2]);   lo.w = pk16(v[11], v[10]);
    hi.x = pk16(v[5], v[4]);   hi.y = pk16(v[13], v[12]);
    hi.z = pk16(v[7], v[6]);   hi.w = pk16(v[15], v[14]);
    size_t base = ((size_t)K16 * 512 + n) * 2;
    Bp[base]     = lo;
    Bp[base + 1] = hi;
}

// ---------------------------------------------------------------------------
// GEMM3 (fp16): out = diag(r) * (adj @ g + g)   [8192x512], K=8192
// CTA 128m x 256n, ktile 64, warps 2m x 4n (warp 64x64), double buffered.
// A: LDG fp32 -> cvt f16x2 -> fragment-paired swizzled STS.64.
// B: cp.async raw copy of fragment-packed fp16 gmem buffer.
// ---------------------------------------------------------------------------
#define G3_AB (128 * 64 * 2)                 // 16 KB / A buffer
#define G3_BB (256 * 64 * 2)                 // 32 KB / B buffer
#define G3_SMEM (2 * G3_AB + 2 * G3_BB)      // 96 KB

__global__ __launch_bounds__(256, 1) void gemm3_fp16(
    const float* __restrict__ adj, const uint4* __restrict__ Bp,
    const float* __restrict__ g, const float* __restrict__ rvec,
    float* __restrict__ out) {

    extern __shared__ __align__(16) char smem[];
    char* As = smem;                 // 2 x 16 KB
    char* Bs = smem + 2 * G3_AB;     // 2 x 32 KB

    const int tid  = threadIdx.x;
    const int lane = tid & 31;
    const int wid  = tid >> 5;
    const int wm = wid >> 2;            // 0..1
    const int wn = wid & 3;             // 0..3
    const int m0 = blockIdx.y * 128;
    const int n0 = blockIdx.x * 256;

    float4 va[4][2];

    auto ldA = [&](int kt) {
#pragma unroll
        for (int i = 0; i < 4; i++) {
            int task = tid + i * 256;
            int gq  = task & 7;
            int q   = (task >> 3) & 15;
            int blk = task >> 7;
            const float* p = adj + (size_t)(m0 + blk * 16 + gq) * NN + kt * 64 + q * 4;
            va[i][0] = *reinterpret_cast<const float4*>(p);
            va[i][1] = *reinterpret_cast<const float4*>(p + 8 * NN);
        }
    };
    auto stA = [&](int buf) {
        char* dst = As + buf * G3_AB;
#pragma unroll
        for (int i = 0; i < 4; i++) {
            int task = tid + i * 256;
            int gq  = task & 7;
            int q   = (task >> 3) & 15;
            int blk = task >> 7;
            uint32_t w00 = pk16(va[i][0].y, va[i][0].x);  // (r, k..k+1)
            uint32_t w01 = pk16(va[i][1].y, va[i][1].x);  // (r+8, k..k+1)
            uint32_t w10 = pk16(va[i][0].w, va[i][0].z);  // (r, k+2..k+3)
            uint32_t w11 = pk16(va[i][1].w, va[i][1].z);  // (r+8, k+2..k+3)
            int s = q & 1;
            int kp1 = 2 * q + s;
            int kp2 = 2 * q + 1 - s;
            uint32_t u1 = blk * 256 + kp1 * 8 + (gq ^ ((kp1 & 3) << 1));
            uint32_t u2 = blk * 256 + kp2 * 8 + (gq ^ ((kp2 & 3) << 1));
            uint2 d1 = s ? make_uint2(w10, w11) : make_uint2(w00, w01);
            uint2 d2 = s ? make_uint2(w00, w01) : make_uint2(w10, w11);
            *reinterpret_cast<uint2*>(dst + u1 * 8) = d1;
            *reinterpret_cast<uint2*>(dst + u2 * 8) = d2;
        }
    };
    auto cpB = [&](int kt, int buf) {
        uint32_t dst = smem_u32(Bs + buf * G3_BB);
        const char* src = reinterpret_cast<const char*>(Bp)
                        + ((size_t)(kt * 4) * 512 + n0) * 32;
#pragma unroll
        for (int j = 0; j < 4; j++)
#pragma unroll
            for (int t = 0; t < 2; t++) {
                int c = tid + t * 256;
                CP_ASYNC16(dst + j * 8192 + c * 16,
                           src + (size_t)j * 512 * 32 + c * 16);
            }
    };

    float acc[4][8][4];
#pragma unroll
    for (int mi = 0; mi < 4; mi++)
#pragma unroll
        for (int nj = 0; nj < 8; nj++)
#pragma unroll
            for (int q = 0; q < 4; q++) acc[mi][nj][q] = 0.f;

    // prologue
    ldA(0);
    cpB(0, 0);
    CP_COMMIT();
    stA(0);
    CP_WAIT0();
    __syncthreads();

    const int gg = lane >> 2;
    const int t4 = lane & 3;

    for (int kt = 0; kt < NN / 64; kt++) {
        const int buf = kt & 1;
        const bool more = (kt + 1 < NN / 64);
        if (more) {
            ldA(kt + 1);
            cpB(kt + 1, buf ^ 1);
            CP_COMMIT();
        }

        const char* Ab = As + buf * G3_AB;
        const char* Bb = Bs + buf * G3_BB;

#pragma unroll
        for (int ks = 0; ks < 4; ks++) {
            uint32_t af[4][4];
#pragma unroll
            for (int mi = 0; mi < 4; mi++) {
                int blk = wm * 4 + mi;
                const char* p = Ab
                    + (size_t)(blk * 256 + (ks * 8 + t4) * 8 + (gg ^ (t4 << 1))) * 8;
                uint2 x = *reinterpret_cast<const uint2*>(p);
                uint2 y = *reinterpret_cast<const uint2*>(p + 256);
                af[mi][0] = x.x; af[mi][1] = x.y;
                af[mi][2] = y.x; af[mi][3] = y.y;
            }
            uint32_t bf[8][2];
#pragma unroll
            for (int nj = 0; nj < 8; nj++) {
                const char* p = Bb
                    + (size_t)(((ks * 256 + wn * 64 + nj * 8 + gg) * 4) + t4) * 8;
                uint2 x = *reinterpret_cast<const uint2*>(p);
                bf[nj][0] = x.x; bf[nj][1] = x.y;
            }
#pragma unroll
            for (int mi = 0; mi < 4; mi++)
#pragma unroll
                for (int nj = 0; nj < 8; nj++)
                    mma_fp16(acc[mi][nj], af[mi], bf[nj]);
        }

        if (more) stA(buf ^ 1);
        CP_WAIT0();
        __syncthreads();
    }

    // epilogue: out = r * (acc + g)
#pragma unroll
    for (int mi = 0; mi < 4; mi++) {
#pragma unroll
        for (int h = 0; h < 2; h++) {
            int row = m0 + wm * 64 + mi * 16 + gg + h * 8;
            float rv = rvec[row];
            const float* gp = g + (size_t)row * OUTF;
            float* op = out + (size_t)row * OUTF;
#pragma unroll
            for (int nj = 0; nj < 8; nj++) {
                int col = n0 + wn * 64 + nj * 8 + t4 * 2;
                float2 gv = *reinterpret_cast<const float2*>(gp + col);
                float2 o;
                o.x = rv * (acc[mi][nj][h * 2 + 0] + gv.x);
                o.y = rv * (acc[mi][nj][h * 2 + 1] + gv.y);
                *reinterpret_cast<float2*>(op + col) = o;
            }
        }
    }
}

// ---------------------------------------------------------------------------
extern "C" void kernel_launch(void* const* d_in, const int* in_sizes, int n_in,
                              void* d_out, int out_size) {
    const float* x   = (const float*)d_in[0];
    const float* adj = (const float*)d_in[1];
    const float* W1  = (const float*)d_in[2];
    const float* b1  = (const float*)d_in[3];
    const float* W2  = (const float*)d_in[4];
    const float* b2  = (const float*)d_in[5];
    float* out = (float*)d_out;

    float *h1p, *gp, *rp;
    uint4* Bpp;
    cudaGetSymbolAddress((void**)&h1p, g_h1);
    cudaGetSymbolAddress((void**)&gp, g_gbuf);
    cudaGetSymbolAddress((void**)&Bpp, g_Bp);
    cudaGetSymbolAddress((void**)&rp, g_r);

    cudaFuncSetAttribute(gemm3_fp16, cudaFuncAttributeMaxDynamicSharedMemorySize,
                         G3_SMEM);

    // r = rsqrt(rowsum(adj)+1)
    rowsum_kernel<<<NN, 256>>>(adj, rp, NN);
    // h1 = x @ W1^T + b1                    [8192,256]
    gemm_tf32<0><<<dim3(HID / 128, NN / 128), 256>>>(
        x, W1, h1p, NN, HID, 512, b1, nullptr);
    // g = r ⊙ (h1 @ W2^T + b2)              [8192,512]  (fp32)
    gemm_tf32<1><<<dim3(OUTF / 128, NN / 128), 256>>>(
        h1p, W2, gp, NN, OUTF, HID, b2, rp);
    // pack g -> fragment-packed fp16 B
    pack_fp16<<<dim3(512, 4), 128>>>(gp, Bpp);
    // out = diag(r) * (adj @ g + g)         [8192,512]  (fp16 MMA)
    gemm3_fp16<<<dim3(2, 64), 256, G3_SMEM>>>(adj, Bpp, gp, rp, out);
}

// round 5
// speedup vs baseline: 1.9577x; 1.2393x over previous
#include <cuda_runtime.h>
#include <cstdint>

// ---------------------------------------------------------------------------
// GCN layer:  out = D^-1/2 (adj+I) D^-1/2 @ ((x@W1^T+b1)@W2^T + b2)
// Folded:  r = rsqrt(rowsum(adj)+1); h1 = x@W1^T+b1;
//          g = r ⊙ (h1@W2^T+b2);     out = diag(r) * (adj@g + g)
// GEMM3: fp16 mma.sync m16n8k16. Both operands pre-packed in gmem in the
// exact smem fragment layout -> main loop is cp.async + LDS + HMMA only,
// 3-stage pipeline, 16 warps. rowsum fused with the adj->fp16 pack.
// ---------------------------------------------------------------------------

#define NN   8192
#define HID  256
#define OUTF 512

__device__ float g_h1[NN * HID];        // 8 MB
__device__ float g_gbuf[NN * OUTF];     // 16 MB  g (fp32, row-major)
__device__ uint4 g_Bp[512 * 512 * 2];   // 8 MB   g fragment-packed fp16
__device__ uint2 g_Ap[512 * 128 * 256]; // 128 MB adj fragment-packed fp16
__device__ float g_r[NN];

__device__ __forceinline__ uint32_t f2tf(float f) {
    uint32_t u;
    asm("cvt.rna.tf32.f32 %0, %1;" : "=r"(u) : "f"(f));
    return u;
}
// pack {lo, hi} floats into f16x2 (lo in bits[15:0])
__device__ __forceinline__ uint32_t pk16(float hi, float lo) {
    uint32_t u;
    asm("cvt.rn.f16x2.f32 %0, %1, %2;" : "=r"(u) : "f"(hi), "f"(lo));
    return u;
}
__device__ __forceinline__ uint32_t smem_u32(const void* p) {
    uint32_t a;
    asm("{ .reg .u64 t; cvta.to.shared.u64 t, %1; cvt.u32.u64 %0, t; }"
        : "=r"(a) : "l"(p));
    return a;
}
__device__ __forceinline__ void mma_tf32(float* c, const uint32_t* a,
                                         uint32_t b0, uint32_t b1) {
    asm volatile(
        "mma.sync.aligned.m16n8k8.row.col.f32.tf32.tf32.f32 "
        "{%0,%1,%2,%3},{%4,%5,%6,%7},{%8,%9},{%0,%1,%2,%3};"
        : "+f"(c[0]), "+f"(c[1]), "+f"(c[2]), "+f"(c[3])
        : "r"(a[0]), "r"(a[1]), "r"(a[2]), "r"(a[3]), "r"(b0), "r"(b1));
}
__device__ __forceinline__ void mma_fp16(float* c, const uint32_t* a,
                                         const uint32_t* b) {
    asm volatile(
        "mma.sync.aligned.m16n8k16.row.col.f32.f16.f16.f32 "
        "{%0,%1,%2,%3},{%4,%5,%6,%7},{%8,%9},{%0,%1,%2,%3};"
        : "+f"(c[0]), "+f"(c[1]), "+f"(c[2]), "+f"(c[3])
        : "r"(a[0]), "r"(a[1]), "r"(a[2]), "r"(a[3]), "r"(b[0]), "r"(b[1]));
}

#define CP_ASYNC16(dst, src) \
    asm volatile("cp.async.cg.shared.global [%0], [%1], 16;" \
                 :: "r"(dst), "l"(src) : "memory")
#define CP_COMMIT() asm volatile("cp.async.commit_group;" ::: "memory")
#define CP_WAIT0()  asm volatile("cp.async.wait_group 0;" ::: "memory")
#define CP_WAIT1()  asm volatile("cp.async.wait_group 1;" ::: "memory")

// ---------------------------------------------------------------------------
// rowsum + adj->fp16 fragment pack.
// Block = one 16-row band (blk16). Ap layout (uint2 units, 8 B):
//   Ap[(blk16*128 + kt)*256 + kpl*8 + gx],  kt = k/64, kpl = (k%64)/2,
//   gx = g ^ ((kpl&3)<<1),  unit = { f16x2(row g, k,k+1), f16x2(row g+8, k,k+1) }
// This is byte-identical to GEMM3's smem stage layout -> raw cp.async copy.
// Also r[i] = rsqrt(rowsum(adj)+1).
// ---------------------------------------------------------------------------
__global__ __launch_bounds__(256) void rowsum_pack(const float* __restrict__ adj,
                                                   float* __restrict__ r,
                                                   uint2* __restrict__ Ap) {
    const int blk = blockIdx.x;           // 0..511
    const int M0  = blk * 16;
    const int g    = threadIdx.x >> 5;    // 0..7  (warp id)
    const int lane = threadIdx.x & 31;    // kpl

    __shared__ uint2 sm[256];

    const float2* p0 = reinterpret_cast<const float2*>(
        adj + (size_t)(M0 + g) * NN) + lane;
    const float2* p1 = reinterpret_cast<const float2*>(
        adj + (size_t)(M0 + g + 8) * NN) + lane;

    const int gx = g ^ ((lane & 3) << 1);
    float s0 = 0.f, s1 = 0.f;

    float2 c0 = p0[0], c1 = p1[0];
    for (int kt = 0; kt < 128; kt++) {
        float2 n0, n1;
        if (kt < 127) { n0 = p0[(kt + 1) * 32]; n1 = p1[(kt + 1) * 32]; }
        s0 += c0.x + c0.y;
        s1 += c1.x + c1.y;
        uint2 u;
        u.x = pk16(c0.y, c0.x);
        u.y = pk16(c1.y, c1.x);
        sm[lane * 8 + gx] = u;
        __syncthreads();
        Ap[((size_t)blk * 128 + kt) * 256 + threadIdx.x] = sm[threadIdx.x];
        __syncthreads();
        c0 = n0; c1 = n1;
    }
    for (int o = 16; o > 0; o >>= 1) {
        s0 += __shfl_down_sync(0xffffffffu, s0, o);
        s1 += __shfl_down_sync(0xffffffffu, s1, o);
    }
    if (lane == 0) {
        r[M0 + g]     = rsqrtf(s0 + 1.0f);
        r[M0 + g + 8] = rsqrtf(s1 + 1.0f);
    }
}

// ---------------------------------------------------------------------------
// Small dense GEMMs (tf32):  C = A @ B^T
// EPI=0: C = acc + bias[col];  EPI=1: C = rvec[row]*(acc+bias[col])
// ---------------------------------------------------------------------------
template <int EPI>
__global__ __launch_bounds__(256) void gemm_tf32(
    const float* __restrict__ A, const float* __restrict__ B, float* __restrict__ C,
    int M, int N, int K,
    const float* __restrict__ bias, const float* __restrict__ rvec) {

    __shared__ __align__(16) float As[128 * 36];
    __shared__ __align__(16) float Bs[128 * 36];

    const int tid  = threadIdx.x;
    const int lane = tid & 31;
    const int warp = tid >> 5;
    const int wm = warp >> 1;
    const int wn = warp & 1;
    const int m0 = blockIdx.y * 128;
    const int n0 = blockIdx.x * 128;
    const int KT = K / 32;

    float acc[2][8][4];
#pragma unroll
    for (int mi = 0; mi < 2; mi++)
#pragma unroll
        for (int nj = 0; nj < 8; nj++)
#pragma unroll
            for (int q = 0; q < 4; q++) acc[mi][nj][q] = 0.f;

    float4 pa[4], pb[4];

    auto loadA = [&](int kt, float4* p) {
#pragma unroll
        for (int i = 0; i < 4; i++) {
            int idx = tid + i * 256;
            int row = idx >> 3;
            int kc  = (idx & 7) << 2;
            p[i] = *reinterpret_cast<const float4*>(
                &A[(size_t)(m0 + row) * K + kt * 32 + kc]);
        }
    };
    auto storeA = [&](const float4* p) {
#pragma unroll
        for (int i = 0; i < 4; i++) {
            int idx = tid + i * 256;
            int row = idx >> 3;
            int kc  = (idx & 7) << 2;
            uint4 t = make_uint4(f2tf(p[i].x), f2tf(p[i].y), f2tf(p[i].z), f2tf(p[i].w));
            *reinterpret_cast<uint4*>(&As[row * 36 + kc]) = t;
        }
    };
    auto loadB = [&](int kt, float4* p) {
#pragma unroll
        for (int i = 0; i < 4; i++) {
            int idx = tid + i * 256;
            int row = idx >> 3;
            int kc  = (idx & 7) << 2;
            p[i] = *reinterpret_cast<const float4*>(
                &B[(size_t)(n0 + row) * K + kt * 32 + kc]);
        }
    };
    auto storeB = [&](const float4* p) {
#pragma unroll
        for (int i = 0; i < 4; i++) {
            int idx = tid + i * 256;
            int row = idx >> 3;
            int kc  = (idx & 7) << 2;
            uint4 t = make_uint4(f2tf(p[i].x), f2tf(p[i].y), f2tf(p[i].z), f2tf(p[i].w));
            *reinterpret_cast<uint4*>(&Bs[row * 36 + kc]) = t;
        }
    };

    loadA(0, pa); loadB(0, pb);
    storeA(pa);   storeB(pb);
    __syncthreads();

    for (int kt = 0; kt < KT; kt++) {
        if (kt + 1 < KT) { loadA(kt + 1, pa); loadB(kt + 1, pb); }

#pragma unroll
        for (int kk = 0; kk < 4; kk++) {
            uint32_t afr[2][4];
#pragma unroll
            for (int mi = 0; mi < 2; mi++) {
                int r0 = wm * 32 + mi * 16 + (lane >> 2);
                int kb = kk * 8 + (lane & 3);
                afr[mi][0] = __float_as_uint(As[r0 * 36 + kb]);
                afr[mi][1] = __float_as_uint(As[(r0 + 8) * 36 + kb]);
                afr[mi][2] = __float_as_uint(As[r0 * 36 + kb + 4]);
                afr[mi][3] = __float_as_uint(As[(r0 + 8) * 36 + kb + 4]);
            }
#pragma unroll
            for (int nj = 0; nj < 8; nj++) {
                int nn = wn * 64 + nj * 8 + (lane >> 2);
                int k0 = kk * 8 + (lane & 3);
                uint32_t b0 = __float_as_uint(Bs[nn * 36 + k0]);
                uint32_t b1 = __float_as_uint(Bs[nn * 36 + k0 + 4]);
                mma_tf32(acc[0][nj], afr[0], b0, b1);
                mma_tf32(acc[1][nj], afr[1], b0, b1);
            }
        }
        __syncthreads();
        if (kt + 1 < KT) {
            storeA(pa); storeB(pb);
            __syncthreads();
        }
    }

    const int lr  = lane >> 2;
    const int lc2 = (lane & 3) * 2;
#pragma unroll
    for (int mi = 0; mi < 2; mi++) {
#pragma unroll
        for (int nj = 0; nj < 8; nj++) {
            int row = m0 + wm * 32 + mi * 16 + lr;
            int col = n0 + wn * 64 + nj * 8 + lc2;
            const float* cc = acc[mi][nj];
#pragma unroll
            for (int half = 0; half < 2; half++) {
                int rr = row + half * 8;
                float v0 = cc[half * 2 + 0];
                float v1 = cc[half * 2 + 1];
                float2 o;
                if (EPI == 0) {
                    o.x = v0 + bias[col];
                    o.y = v1 + bias[col + 1];
                } else {
                    float rv = rvec[rr];
                    o.x = rv * (v0 + bias[col]);
                    o.y = rv * (v1 + bias[col + 1]);
                }
                *reinterpret_cast<float2*>(&C[(size_t)rr * N + col]) = o;
            }
        }
    }
}

// ---------------------------------------------------------------------------
// Pack g (fp32 [8192,512]) into fragment-packed fp16 B operand.
// Unit (K16, n, t4) at byte ((K16*512+n)*32 + t4*8):
//   word0 = f16x2{g[K16*16+2t4][n], [..+1][n]}, word1 = {..+8, ..+9}.
// ---------------------------------------------------------------------------
__global__ __launch_bounds__(128) void pack_fp16(const float* __restrict__ g,
                                                 uint4* __restrict__ Bp) {
    const int K16 = blockIdx.x;
    const int n   = blockIdx.y * 128 + threadIdx.x;
    float v[16];
#pragma unroll
    for (int kin = 0; kin < 16; kin++)
        v[kin] = g[(size_t)(K16 * 16 + kin) * OUTF + n];
    uint4 lo, hi;
    lo.x = pk16(v[1], v[0]);   lo.y = pk16(v[9], v[8]);
    lo.z = pk16(v[3], v[2]);   lo.w = pk16(v[11], v[10]);
    hi.x = pk16(v[5], v[4]);   hi.y = pk16(v[13], v[12]);
    hi.z = pk16(v[7], v[6]);   hi.w = pk16(v[15], v[14]);
    size_t base = ((size_t)K16 * 512 + n) * 2;
    Bp[base]     = lo;
    Bp[base + 1] = hi;
}

// ---------------------------------------------------------------------------
// GEMM3 (fp16): out = diag(r) * (adj @ g + g)   [8192x512], K=8192
// CTA 128m x 256n, ktile 64, 512 threads, warp grid 4m x 4n (warp 32x64).
// 3-stage cp.async pipeline; both operands raw-copied from pre-packed gmem.
// ---------------------------------------------------------------------------
#define G3_S   3
#define G3_AB  16384                     // A stage bytes
#define G3_BB  32768                     // B stage bytes
#define G3_SMEM (G3_S * (G3_AB + G3_BB)) // 144 KB

__global__ __launch_bounds__(512, 1) void gemm3_fp16(
    const uint2* __restrict__ Ap, const uint4* __restrict__ Bp,
    const float* __restrict__ g, const float* __restrict__ rvec,
    float* __restrict__ out) {

    extern __shared__ __align__(16) char smem[];
    char* smA = smem;                    // 3 x 16 KB
    char* smB = smem + G3_S * G3_AB;     // 3 x 32 KB

    const int tid  = threadIdx.x;
    const int lane = tid & 31;
    const int wid  = tid >> 5;
    const int wm = wid >> 2;             // 0..3
    const int wn = wid & 3;              // 0..3
    const int m0 = blockIdx.y * 128;
    const int n0 = blockIdx.x * 256;
    const int blk16base = m0 >> 4;

    const char* ApB = reinterpret_cast<const char*>(Ap);
    const char* BpB = reinterpret_cast<const char*>(Bp);

    auto issue = [&](int kt, int slot) {
        uint32_t dA = smem_u32(smA + slot * G3_AB);
        uint32_t dB = smem_u32(smB + slot * G3_BB);
        // A: 8 chunks of 2 KB, one per blk16
#pragma unroll
        for (int i = 0; i < 2; i++) {
            int task = tid + i * 512;              // 0..1023 (16B units)
            int blk = task >> 7;
            int off = task & 127;
            const char* s = ApB + (((size_t)(blk16base + blk) * 128 + kt) * 256
                                   + (size_t)off * 2) * 8;
            CP_ASYNC16(dA + task * 16, s);
        }
        // B: 4 chunks of 8 KB, one per K16 (= kt*4+ks)
#pragma unroll
        for (int i = 0; i < 4; i++) {
            int task = tid + i * 512;              // 0..2047 (16B units)
            int ks  = task >> 9;
            int off = task & 511;
            const char* s = BpB + ((size_t)(kt * 4 + ks) * 512 + n0) * 32
                          + (size_t)off * 16;
            CP_ASYNC16(dB + task * 16, s);
        }
        CP_COMMIT();
    };

    float acc[2][8][4];
#pragma unroll
    for (int mi = 0; mi < 2; mi++)
#pragma unroll
        for (int nj = 0; nj < 8; nj++)
#pragma unroll
            for (int q = 0; q < 4; q++) acc[mi][nj][q] = 0.f;

    // prologue: stages 0..S-2
    issue(0, 0);
    issue(1, 1);

    const int g8 = lane >> 2;            // 0..7
    const int t4 = lane & 3;             // 0..3
    const int axor = (g8 ^ (t4 << 1));

    for (int kt = 0; kt < NN / 64; kt++) {
        const int slot = kt % G3_S;
        if (kt + 2 < NN / 64) { CP_WAIT1(); } else { CP_WAIT0(); }
        __syncthreads();
        if (kt + G3_S - 1 < NN / 64) issue(kt + G3_S - 1, (kt + G3_S - 1) % G3_S);

        const char* Ab = smA + slot * G3_AB;
        const char* Bb = smB + slot * G3_BB;

#pragma unroll
        for (int ks = 0; ks < 4; ks++) {
            uint32_t af[2][4];
#pragma unroll
            for (int mi = 0; mi < 2; mi++) {
                int blk = wm * 2 + mi;
                const char* p = Ab
                    + (size_t)(blk * 256 + (ks * 8 + t4) * 8 + axor) * 8;
                uint2 x = *reinterpret_cast<const uint2*>(p);
                uint2 y = *reinterpret_cast<const uint2*>(p + 256);
                af[mi][0] = x.x; af[mi][1] = x.y;
                af[mi][2] = y.x; af[mi][3] = y.y;
            }
            uint32_t bf[8][2];
#pragma unroll
            for (int nj = 0; nj < 8; nj++) {
                const char* p = Bb
                    + (size_t)(((ks * 256 + wn * 64 + nj * 8 + g8) * 4) + t4) * 8;
                uint2 x = *reinterpret_cast<const uint2*>(p);
                bf[nj][0] = x.x; bf[nj][1] = x.y;
            }
#pragma unroll
            for (int mi = 0; mi < 2; mi++)
#pragma unroll
                for (int nj = 0; nj < 8; nj++)
                    mma_fp16(acc[mi][nj], af[mi], bf[nj]);
        }
        __syncthreads();
    }

    // epilogue: out = r * (acc + g)
#pragma unroll
    for (int mi = 0; mi < 2; mi++) {
#pragma unroll
        for (int h = 0; h < 2; h++) {
            int row = m0 + wm * 32 + mi * 16 + g8 + h * 8;
            float rv = rvec[row];
            const float* gp = g + (size_t)row * OUTF;
            float* op = out + (size_t)row * OUTF;
#pragma unroll
            for (int nj = 0; nj < 8; nj++) {
                int col = n0 + wn * 64 + nj * 8 + t4 * 2;
                float2 gv = *reinterpret_cast<const float2*>(gp + col);
                float2 o;
                o.x = rv * (acc[mi][nj][h * 2 + 0] + gv.x);
                o.y = rv * (acc[mi][nj][h * 2 + 1] + gv.y);
                *reinterpret_cast<float2*>(op + col) = o;
            }
        }
    }
}

// ---------------------------------------------------------------------------
extern "C" void kernel_launch(void* const* d_in, const int* in_sizes, int n_in,
                              void* d_out, int out_size) {
    const float* x   = (const float*)d_in[0];
    const float* adj = (const float*)d_in[1];
    const float* W1  = (const float*)d_in[2];
    const float* b1  = (const float*)d_in[3];
    const float* W2  = (const float*)d_in[4];
    const float* b2  = (const float*)d_in[5];
    float* out = (float*)d_out;

    float *h1p, *gp, *rp;
    uint4* Bpp;
    uint2* App;
    cudaGetSymbolAddress((void**)&h1p, g_h1);
    cudaGetSymbolAddress((void**)&gp, g_gbuf);
    cudaGetSymbolAddress((void**)&Bpp, g_Bp);
    cudaGetSymbolAddress((void**)&App, g_Ap);
    cudaGetSymbolAddress((void**)&rp, g_r);

    cudaFuncSetAttribute(gemm3_fp16, cudaFuncAttributeMaxDynamicSharedMemorySize,
                         G3_SMEM);

    // r = rsqrt(rowsum(adj)+1), Ap = fragment-packed fp16 adj
    rowsum_pack<<<512, 256>>>(adj, rp, App);
    // h1 = x @ W1^T + b1                    [8192,256]
    gemm_tf32<0><<<dim3(HID / 128, NN / 128), 256>>>(
        x, W1, h1p, NN, HID, 512, b1, nullptr);
    // g = r ⊙ (h1 @ W2^T + b2)              [8192,512]  (fp32)
    gemm_tf32<1><<<dim3(OUTF / 128, NN / 128), 256>>>(
        h1p, W2, gp, NN, OUTF, HID, b2, rp);
    // pack g -> fragment-packed fp16 B
    pack_fp16<<<dim3(512, 4), 128>>>(gp, Bpp);
    // out = diag(r) * (adj @ g + g)         [8192,512]  (fp16 MMA)
    gemm3_fp16<<<dim3(2, 64), 512, G3_SMEM>>>(App, Bpp, gp, rp, out);
}

// round 6
// speedup vs baseline: 2.1296x; 1.0878x over previous
#include <cuda_runtime.h>
#include <cstdint>

// ---------------------------------------------------------------------------
// GCN layer:  out = D^-1/2 (adj+I) D^-1/2 @ ((x@W1^T+b1)@W2^T + b2)
// Folded:  r = rsqrt(rowsum(adj)+1); h1 = x@W1^T+b1;
//          g = r ⊙ (h1@W2^T+b2);     out = diag(r) * (adj@g + g)
// GEMM3: fp16 mma.sync m16n8k16, warp tile 64x64, 4-stage cp.async pipeline,
// both operands pre-packed in gmem in smem fragment layout.
// ---------------------------------------------------------------------------

#define NN   8192
#define HID  256
#define OUTF 512

__device__ float g_h1[NN * HID];        // 8 MB
__device__ float g_gbuf[NN * OUTF];     // 16 MB  g (fp32, row-major)
__device__ uint4 g_Bp[512 * 512 * 2];   // 8 MB   g fragment-packed fp16
__device__ uint2 g_Ap[512 * 128 * 256]; // 128 MB adj fragment-packed fp16
__device__ float g_r[NN];

__device__ __forceinline__ uint32_t f2tf(float f) {
    uint32_t u;
    asm("cvt.rna.tf32.f32 %0, %1;" : "=r"(u) : "f"(f));
    return u;
}
// pack {lo, hi} floats into f16x2 (lo in bits[15:0])
__device__ __forceinline__ uint32_t pk16(float hi, float lo) {
    uint32_t u;
    asm("cvt.rn.f16x2.f32 %0, %1, %2;" : "=r"(u) : "f"(hi), "f"(lo));
    return u;
}
__device__ __forceinline__ uint32_t smem_u32(const void* p) {
    uint32_t a;
    asm("{ .reg .u64 t; cvta.to.shared.u64 t, %1; cvt.u32.u64 %0, t; }"
        : "=r"(a) : "l"(p));
    return a;
}
__device__ __forceinline__ void mma_tf32(float* c, const uint32_t* a,
                                         uint32_t b0, uint32_t b1) {
    asm volatile(
        "mma.sync.aligned.m16n8k8.row.col.f32.tf32.tf32.f32 "
        "{%0,%1,%2,%3},{%4,%5,%6,%7},{%8,%9},{%0,%1,%2,%3};"
        : "+f"(c[0]), "+f"(c[1]), "+f"(c[2]), "+f"(c[3])
        : "r"(a[0]), "r"(a[1]), "r"(a[2]), "r"(a[3]), "r"(b0), "r"(b1));
}
__device__ __forceinline__ void mma_fp16(float* c, const uint32_t* a,
                                         const uint32_t* b) {
    asm volatile(
        "mma.sync.aligned.m16n8k16.row.col.f32.f16.f16.f32 "
        "{%0,%1,%2,%3},{%4,%5,%6,%7},{%8,%9},{%0,%1,%2,%3};"
        : "+f"(c[0]), "+f"(c[1]), "+f"(c[2]), "+f"(c[3])
        : "r"(a[0]), "r"(a[1]), "r"(a[2]), "r"(a[3]), "r"(b[0]), "r"(b[1]));
}

#define CP_ASYNC16(dst, src) \
    asm volatile("cp.async.cg.shared.global [%0], [%1], 16;" \
                 :: "r"(dst), "l"(src) : "memory")
#define CP_COMMIT() asm volatile("cp.async.commit_group;" ::: "memory")
#define CP_WAIT0()  asm volatile("cp.async.wait_group 0;" ::: "memory")
#define CP_WAIT1()  asm volatile("cp.async.wait_group 1;" ::: "memory")
#define CP_WAIT2()  asm volatile("cp.async.wait_group 2;" ::: "memory")

// ---------------------------------------------------------------------------
// rowsum + adj->fp16 fragment pack.
// Ap layout (uint2 units): Ap[(blk16*128 + kt)*256 + kpl*8 + gx],
//   kpl=(k%64)/2, gx = g ^ ((kpl&3)<<1),
//   unit = { f16x2(row g, k..k+1), f16x2(row g+8, k..k+1) }.
// Staging uses stride-9 padding (<=2-way conflicts) and 4-kt batches.
// ---------------------------------------------------------------------------
__global__ __launch_bounds__(256) void rowsum_pack(const float* __restrict__ adj,
                                                   float* __restrict__ r,
                                                   uint2* __restrict__ Ap) {
    const int blk  = blockIdx.x;          // 0..511
    const int M0   = blk * 16;
    const int g    = threadIdx.x >> 5;    // 0..7 (warp id = row group)
    const int lane = threadIdx.x & 31;    // k-pair within ktile64

    __shared__ uint2 sm[4][32 * 9];

    const float2* p0 = reinterpret_cast<const float2*>(
        adj + (size_t)(M0 + g) * NN) + lane;
    const float2* p1 = reinterpret_cast<const float2*>(
        adj + (size_t)(M0 + g + 8) * NN) + lane;

    const int sidx = lane * 9 + (g ^ ((lane & 3) << 1));
    const int ridx = (threadIdx.x >> 3) * 9 + (threadIdx.x & 7);

    float s0 = 0.f, s1 = 0.f;

    for (int ot = 0; ot < 32; ot++) {
        float2 c0[4], c1[4];
#pragma unroll
        for (int sub = 0; sub < 4; sub++) {
            c0[sub] = p0[(ot * 4 + sub) * 32];
            c1[sub] = p1[(ot * 4 + sub) * 32];
        }
#pragma unroll
        for (int sub = 0; sub < 4; sub++) {
            s0 += c0[sub].x + c0[sub].y;
            s1 += c1[sub].x + c1[sub].y;
            uint2 u;
            u.x = pk16(c0[sub].y, c0[sub].x);
            u.y = pk16(c1[sub].y, c1[sub].x);
            sm[sub][sidx] = u;
        }
        __syncthreads();
#pragma unroll
        for (int sub = 0; sub < 4; sub++)
            Ap[((size_t)blk * 128 + ot * 4 + sub) * 256 + threadIdx.x]
                = sm[sub][ridx];
        __syncthreads();
    }

    for (int o = 16; o > 0; o >>= 1) {
        s0 += __shfl_down_sync(0xffffffffu, s0, o);
        s1 += __shfl_down_sync(0xffffffffu, s1, o);
    }
    if (lane == 0) {
        r[M0 + g]     = rsqrtf(s0 + 1.0f);
        r[M0 + g + 8] = rsqrtf(s1 + 1.0f);
    }
}

// ---------------------------------------------------------------------------
// Small dense GEMMs (tf32):  C = A @ B^T
// EPI=0: C = acc + bias[col];  EPI=1: C = rvec[row]*(acc+bias[col])
// ---------------------------------------------------------------------------
template <int EPI>
__global__ __launch_bounds__(256) void gemm_tf32(
    const float* __restrict__ A, const float* __restrict__ B, float* __restrict__ C,
    int M, int N, int K,
    const float* __restrict__ bias, const float* __restrict__ rvec) {

    __shared__ __align__(16) float As[128 * 36];
    __shared__ __align__(16) float Bs[128 * 36];

    const int tid  = threadIdx.x;
    const int lane = tid & 31;
    const int warp = tid >> 5;
    const int wm = warp >> 1;
    const int wn = warp & 1;
    const int m0 = blockIdx.y * 128;
    const int n0 = blockIdx.x * 128;
    const int KT = K / 32;

    float acc[2][8][4];
#pragma unroll
    for (int mi = 0; mi < 2; mi++)
#pragma unroll
        for (int nj = 0; nj < 8; nj++)
#pragma unroll
            for (int q = 0; q < 4; q++) acc[mi][nj][q] = 0.f;

    float4 pa[4], pb[4];

    auto loadA = [&](int kt, float4* p) {
#pragma unroll
        for (int i = 0; i < 4; i++) {
            int idx = tid + i * 256;
            int row = idx >> 3;
            int kc  = (idx & 7) << 2;
            p[i] = *reinterpret_cast<const float4*>(
                &A[(size_t)(m0 + row) * K + kt * 32 + kc]);
        }
    };
    auto storeA = [&](const float4* p) {
#pragma unroll
        for (int i = 0; i < 4; i++) {
            int idx = tid + i * 256;
            int row = idx >> 3;
            int kc  = (idx & 7) << 2;
            uint4 t = make_uint4(f2tf(p[i].x), f2tf(p[i].y), f2tf(p[i].z), f2tf(p[i].w));
            *reinterpret_cast<uint4*>(&As[row * 36 + kc]) = t;
        }
    };
    auto loadB = [&](int kt, float4* p) {
#pragma unroll
        for (int i = 0; i < 4; i++) {
            int idx = tid + i * 256;
            int row = idx >> 3;
            int kc  = (idx & 7) << 2;
            p[i] = *reinterpret_cast<const float4*>(
                &B[(size_t)(n0 + row) * K + kt * 32 + kc]);
        }
    };
    auto storeB = [&](const float4* p) {
#pragma unroll
        for (int i = 0; i < 4; i++) {
            int idx = tid + i * 256;
            int row = idx >> 3;
            int kc  = (idx & 7) << 2;
            uint4 t = make_uint4(f2tf(p[i].x), f2tf(p[i].y), f2tf(p[i].z), f2tf(p[i].w));
            *reinterpret_cast<uint4*>(&Bs[row * 36 + kc]) = t;
        }
    };

    loadA(0, pa); loadB(0, pb);
    storeA(pa);   storeB(pb);
    __syncthreads();

    for (int kt = 0; kt < KT; kt++) {
        if (kt + 1 < KT) { loadA(kt + 1, pa); loadB(kt + 1, pb); }

#pragma unroll
        for (int kk = 0; kk < 4; kk++) {
            uint32_t afr[2][4];
#pragma unroll
            for (int mi = 0; mi < 2; mi++) {
                int r0 = wm * 32 + mi * 16 + (lane >> 2);
                int kb = kk * 8 + (lane & 3);
                afr[mi][0] = __float_as_uint(As[r0 * 36 + kb]);
                afr[mi][1] = __float_as_uint(As[(r0 + 8) * 36 + kb]);
                afr[mi][2] = __float_as_uint(As[r0 * 36 + kb + 4]);
                afr[mi][3] = __float_as_uint(As[(r0 + 8) * 36 + kb + 4]);
            }
#pragma unroll
            for (int nj = 0; nj < 8; nj++) {
                int nn = wn * 64 + nj * 8 + (lane >> 2);
                int k0 = kk * 8 + (lane & 3);
                uint32_t b0 = __float_as_uint(Bs[nn * 36 + k0]);
                uint32_t b1 = __float_as_uint(Bs[nn * 36 + k0 + 4]);
                mma_tf32(acc[0][nj], afr[0], b0, b1);
                mma_tf32(acc[1][nj], afr[1], b0, b1);
            }
        }
        __syncthreads();
        if (kt + 1 < KT) {
            storeA(pa); storeB(pb);
            __syncthreads();
        }
    }

    const int lr  = lane >> 2;
    const int lc2 = (lane & 3) * 2;
#pragma unroll
    for (int mi = 0; mi < 2; mi++) {
#pragma unroll
        for (int nj = 0; nj < 8; nj++) {
            int row = m0 + wm * 32 + mi * 16 + lr;
            int col = n0 + wn * 64 + nj * 8 + lc2;
            const float* cc = acc[mi][nj];
#pragma unroll
            for (int half = 0; half < 2; half++) {
                int rr = row + half * 8;
                float v0 = cc[half * 2 + 0];
                float v1 = cc[half * 2 + 1];
                float2 o;
                if (EPI == 0) {
                    o.x = v0 + bias[col];
                    o.y = v1 + bias[col + 1];
                } else {
                    float rv = rvec[rr];
                    o.x = rv * (v0 + bias[col]);
                    o.y = rv * (v1 + bias[col + 1]);
                }
                *reinterpret_cast<float2*>(&C[(size_t)rr * N + col]) = o;
            }
        }
    }
}

// ---------------------------------------------------------------------------
// Pack g (fp32 [8192,512]) into fragment-packed fp16 B operand.
// ---------------------------------------------------------------------------
__global__ __launch_bounds__(128) void pack_fp16(const float* __restrict__ g,
                                                 uint4* __restrict__ Bp) {
    const int K16 = blockIdx.x;
    const int n   = blockIdx.y * 128 + threadIdx.x;
    float v[16];
#pragma unroll
    for (int kin = 0; kin < 16; kin++)
        v[kin] = g[(size_t)(K16 * 16 + kin) * OUTF + n];
    uint4 lo, hi;
    lo.x = pk16(v[1], v[0]);   lo.y = pk16(v[9], v[8]);
    lo.z = pk16(v[3], v[2]);   lo.w = pk16(v[11], v[10]);
    hi.x = pk16(v[5], v[4]);   hi.y = pk16(v[13], v[12]);
    hi.z = pk16(v[7], v[6]);   hi.w = pk16(v[15], v[14]);
    size_t base = ((size_t)K16 * 512 + n) * 2;
    Bp[base]     = lo;
    Bp[base + 1] = hi;
}

// ---------------------------------------------------------------------------
// GEMM3 (fp16): out = diag(r) * (adj @ g + g)   [8192x512], K=8192
// CTA 128m x 256n, 256 threads, warp grid 2m x 4n (warp tile 64x64),
// ktile 64, 4-stage cp.async pipeline (wait_group 2), 1 sync per ktile.
// ---------------------------------------------------------------------------
#define G3_S   4
#define G3_AB  16384                     // A stage bytes
#define G3_BB  32768                     // B stage bytes
#define G3_SMEM (G3_S * (G3_AB + G3_BB)) // 192 KB
#define G3_KT  (NN / 64)                 // 128

__global__ __launch_bounds__(256, 1) void gemm3_fp16(
    const uint2* __restrict__ Ap, const uint4* __restrict__ Bp,
    const float* __restrict__ g, const float* __restrict__ rvec,
    float* __restrict__ out) {

    extern __shared__ __align__(16) char smem[];
    char* smA = smem;                    // 4 x 16 KB
    char* smB = smem + G3_S * G3_AB;     // 4 x 32 KB

    const int tid  = threadIdx.x;
    const int lane = tid & 31;
    const int wid  = tid >> 5;
    const int wm = wid >> 2;             // 0..1
    const int wn = wid & 3;              // 0..3
    const int m0 = blockIdx.y * 128;
    const int n0 = blockIdx.x * 256;
    const int blk16base = m0 >> 4;

    const char* ApB = reinterpret_cast<const char*>(Ap);
    const char* BpB = reinterpret_cast<const char*>(Bp);

    auto issue = [&](int kt, int slot) {
        uint32_t dA = smem_u32(smA + slot * G3_AB);
        uint32_t dB = smem_u32(smB + slot * G3_BB);
        // A: 1024 x 16B granules
#pragma unroll
        for (int i = 0; i < 4; i++) {
            int task = tid + i * 256;
            int blk = task >> 7;
            int off = task & 127;
            const char* s = ApB + ((size_t)(blk16base + blk) * 128 + kt) * 2048
                          + (size_t)off * 16;
            CP_ASYNC16(dA + task * 16, s);
        }
        // B: 2048 x 16B granules
#pragma unroll
        for (int i = 0; i < 8; i++) {
            int task = tid + i * 256;
            int ks  = task >> 9;
            int off = task & 511;
            const char* s = BpB + ((size_t)(kt * 4 + ks) * 512 + n0) * 32
                          + (size_t)off * 16;
            CP_ASYNC16(dB + task * 16, s);
        }
        CP_COMMIT();
    };

    float acc[4][8][4];
#pragma unroll
    for (int mi = 0; mi < 4; mi++)
#pragma unroll
        for (int nj = 0; nj < 8; nj++)
#pragma unroll
            for (int q = 0; q < 4; q++) acc[mi][nj][q] = 0.f;

    // prologue: fill 3 of 4 stages
    issue(0, 0);
    issue(1, 1);
    issue(2, 2);

    const int g8 = lane >> 2;            // 0..7
    const int t4 = lane & 3;             // 0..3
    const int axor = g8 ^ (t4 << 1);

    for (int kt = 0; kt < G3_KT; kt++) {
        const int slot = kt & (G3_S - 1);
        const int rem = G3_KT - 1 - kt;  // groups still issued after this one
        if (rem >= 2)      { CP_WAIT2(); }
        else if (rem == 1) { CP_WAIT1(); }
        else               { CP_WAIT0(); }
        __syncthreads();   // stage data visible; also orders prev consume vs reissue
        if (kt + G3_S - 1 < G3_KT) issue(kt + G3_S - 1, (kt + G3_S - 1) & (G3_S - 1));

        const char* Ab = smA + slot * G3_AB;
        const char* Bb = smB + slot * G3_BB;

#pragma unroll
        for (int ks = 0; ks < 4; ks++) {
            uint32_t af[4][4];
#pragma unroll
            for (int mi = 0; mi < 4; mi++) {
                int blk = wm * 4 + mi;
                const char* p = Ab
                    + (size_t)(blk * 256 + (ks * 8 + t4) * 8 + axor) * 8;
                uint2 x = *reinterpret_cast<const uint2*>(p);
                uint2 y = *reinterpret_cast<const uint2*>(p + 256);
                af[mi][0] = x.x; af[mi][1] = x.y;
                af[mi][2] = y.x; af[mi][3] = y.y;
            }
            uint32_t bf[8][2];
#pragma unroll
            for (int nj = 0; nj < 8; nj++) {
                const char* p = Bb
                    + (size_t)(((ks * 256 + wn * 64 + nj * 8 + g8) * 4) + t4) * 8;
                uint2 x = *reinterpret_cast<const uint2*>(p);
                bf[nj][0] = x.x; bf[nj][1] = x.y;
            }
#pragma unroll
            for (int mi = 0; mi < 4; mi++)
#pragma unroll
                for (int nj = 0; nj < 8; nj++)
                    mma_fp16(acc[mi][nj], af[mi], bf[nj]);
        }
    }

    // epilogue: out = r * (acc + g)
#pragma unroll
    for (int mi = 0; mi < 4; mi++) {
#pragma unroll
        for (int h = 0; h < 2; h++) {
            int row = m0 + wm * 64 + mi * 16 + g8 + h * 8;
            float rv = rvec[row];
            const float* gp = g + (size_t)row * OUTF;
            float* op = out + (size_t)row * OUTF;
#pragma unroll
            for (int nj = 0; nj < 8; nj++) {
                int col = n0 + wn * 64 + nj * 8 + t4 * 2;
                float2 gv = *reinterpret_cast<const float2*>(gp + col);
                float2 o;
                o.x = rv * (acc[mi][nj][h * 2 + 0] + gv.x);
                o.y = rv * (acc[mi][nj][h * 2 + 1] + gv.y);
                *reinterpret_cast<float2*>(op + col) = o;
            }
        }
    }
}

// ---------------------------------------------------------------------------
extern "C" void kernel_launch(void* const* d_in, const int* in_sizes, int n_in,
                              void* d_out, int out_size) {
    const float* x   = (const float*)d_in[0];
    const float* adj = (const float*)d_in[1];
    const float* W1  = (const float*)d_in[2];
    const float* b1  = (const float*)d_in[3];
    const float* W2  = (const float*)d_in[4];
    const float* b2  = (const float*)d_in[5];
    float* out = (float*)d_out;

    float *h1p, *gp, *rp;
    uint4* Bpp;
    uint2* App;
    cudaGetSymbolAddress((void**)&h1p, g_h1);
    cudaGetSymbolAddress((void**)&gp, g_gbuf);
    cudaGetSymbolAddress((void**)&Bpp, g_Bp);
    cudaGetSymbolAddress((void**)&App, g_Ap);
    cudaGetSymbolAddress((void**)&rp, g_r);

    cudaFuncSetAttribute(gemm3_fp16, cudaFuncAttributeMaxDynamicSharedMemorySize,
                         G3_SMEM);

    // r = rsqrt(rowsum(adj)+1), Ap = fragment-packed fp16 adj
    rowsum_pack<<<512, 256>>>(adj, rp, App);
    // h1 = x @ W1^T + b1                    [8192,256]
    gemm_tf32<0><<<dim3(HID / 128, NN / 128), 256>>>(
        x, W1, h1p, NN, HID, 512, b1, nullptr);
    // g = r ⊙ (h1 @ W2^T + b2)              [8192,512]  (fp32)
    gemm_tf32<1><<<dim3(OUTF / 128, NN / 128), 256>>>(
        h1p, W2, gp, NN, OUTF, HID, b2, rp);
    // pack g -> fragment-packed fp16 B
    pack_fp16<<<dim3(512, 4), 128>>>(gp, Bpp);
    // out = diag(r) * (adj @ g + g)         [8192,512]  (fp16 MMA)
    gemm3_fp16<<<dim3(2, 64), 256, G3_SMEM>>>(App, Bpp, gp, rp, out);
}

// round 7
// speedup vs baseline: 2.3198x; 1.0893x over previous
#include <cuda_runtime.h>
#include <cuda_fp16.h>
#include <cstdint>

// ---------------------------------------------------------------------------
// GCN layer:  out = D^-1/2 (adj+I) D^-1/2 @ ((x@W1^T+b1)@W2^T + b2)
// Folded:  r = rsqrt(rowsum(adj)+1); h1 = x@W1^T+b1;
//          g = r ⊙ (h1@W2^T+b2);     out = diag(r) * (adj@g + g)
// Launch chain (3 kernels):
//   fused_pre : rowsum + adj->fp16 fragment pack  UNION  gemm1 (independent)
//   gemm2     : tf32 GEMM, epilogue writes g (fp32) AND fragment-packed fp16 Bp
//   gemm3     : fp16 mma.sync m16n8k16, warp 64x64, 4-stage cp.async pipeline
// ---------------------------------------------------------------------------

#define NN   8192
#define HID  256
#define OUTF 512

__device__ float g_h1[NN * HID];        // 8 MB
__device__ float g_gbuf[NN * OUTF];     // 16 MB  g (fp32, row-major)
__device__ uint4 g_Bp[512 * 512 * 2];   // 8 MB   g fragment-packed fp16
__device__ uint2 g_Ap[512 * 128 * 256]; // 128 MB adj fragment-packed fp16
__device__ float g_r[NN];

__device__ __forceinline__ uint32_t f2tf(float f) {
    uint32_t u;
    asm("cvt.rna.tf32.f32 %0, %1;" : "=r"(u) : "f"(f));
    return u;
}
// pack {lo, hi} floats into f16x2 (lo in bits[15:0])
__device__ __forceinline__ uint32_t pk16(float hi, float lo) {
    uint32_t u;
    asm("cvt.rn.f16x2.f32 %0, %1, %2;" : "=r"(u) : "f"(hi), "f"(lo));
    return u;
}
__device__ __forceinline__ uint32_t smem_u32(const void* p) {
    uint32_t a;
    asm("{ .reg .u64 t; cvta.to.shared.u64 t, %1; cvt.u32.u64 %0, t; }"
        : "=r"(a) : "l"(p));
    return a;
}
__device__ __forceinline__ void mma_tf32(float* c, const uint32_t* a,
                                         uint32_t b0, uint32_t b1) {
    asm volatile(
        "mma.sync.aligned.m16n8k8.row.col.f32.tf32.tf32.f32 "
        "{%0,%1,%2,%3},{%4,%5,%6,%7},{%8,%9},{%0,%1,%2,%3};"
        : "+f"(c[0]), "+f"(c[1]), "+f"(c[2]), "+f"(c[3])
        : "r"(a[0]), "r"(a[1]), "r"(a[2]), "r"(a[3]), "r"(b0), "r"(b1));
}
__device__ __forceinline__ void mma_fp16(float* c, const uint32_t* a,
                                         const uint32_t* b) {
    asm volatile(
        "mma.sync.aligned.m16n8k16.row.col.f32.f16.f16.f32 "
        "{%0,%1,%2,%3},{%4,%5,%6,%7},{%8,%9},{%0,%1,%2,%3};"
        : "+f"(c[0]), "+f"(c[1]), "+f"(c[2]), "+f"(c[3])
        : "r"(a[0]), "r"(a[1]), "r"(a[2]), "r"(a[3]), "r"(b[0]), "r"(b[1]));
}

#define CP_ASYNC16(dst, src) \
    asm volatile("cp.async.cg.shared.global [%0], [%1], 16;" \
                 :: "r"(dst), "l"(src) : "memory")
#define CP_COMMIT() asm volatile("cp.async.commit_group;" ::: "memory")
#define CP_WAIT0()  asm volatile("cp.async.wait_group 0;" ::: "memory")
#define CP_WAIT1()  asm volatile("cp.async.wait_group 1;" ::: "memory")
#define CP_WAIT2()  asm volatile("cp.async.wait_group 2;" ::: "memory")

// ---------------------------------------------------------------------------
// fused_pre:
//   blocks [0,128)   : gemm1  h1 = x @ W1^T + b1   (M=8192, N=256, K=512)
//   blocks [128,640) : rowsum r + adj->fp16 fragment pack into Ap
// Ap layout (uint2): Ap[(blk16*128 + kt)*256 + kpl*8 + gx],
//   kpl=(k%64)/2, gx = g ^ ((kpl&3)<<1),
//   unit = { f16x2(row g, k..k+1), f16x2(row g+8, k..k+1) }.
// ---------------------------------------------------------------------------
#define PRE_SMEM (2 * 128 * 36 * 4)     // 36864 (gemm1 branch is the max)

__global__ __launch_bounds__(256) void fused_pre(
    const float* __restrict__ adj, float* __restrict__ r, uint2* __restrict__ Ap,
    const float* __restrict__ x, const float* __restrict__ W1,
    float* __restrict__ h1, const float* __restrict__ b1) {

    extern __shared__ __align__(16) char dyn[];
    const int tid = threadIdx.x;

    if (blockIdx.x < 128) {
        // ---------------- gemm1: tf32, C = A @ B^T + bias ----------------
        const int M_ = NN, N_ = HID, K_ = 512;
        float* As = reinterpret_cast<float*>(dyn);          // 128*36
        float* Bs = As + 128 * 36;

        const int lane = tid & 31;
        const int warp = tid >> 5;
        const int wm = warp >> 1;
        const int wn = warp & 1;
        const int bx = blockIdx.x;
        const int m0 = (bx >> 1) * 128;
        const int n0 = (bx & 1) * 128;
        const int KT = K_ / 32;

        float acc[2][8][4];
#pragma unroll
        for (int mi = 0; mi < 2; mi++)
#pragma unroll
            for (int nj = 0; nj < 8; nj++)
#pragma unroll
                for (int q = 0; q < 4; q++) acc[mi][nj][q] = 0.f;

        float4 pa[4], pb[4];

        auto loadA = [&](int kt, float4* p) {
#pragma unroll
            for (int i = 0; i < 4; i++) {
                int idx = tid + i * 256;
                int row = idx >> 3;
                int kc  = (idx & 7) << 2;
                p[i] = *reinterpret_cast<const float4*>(
                    &x[(size_t)(m0 + row) * K_ + kt * 32 + kc]);
            }
        };
        auto storeA = [&](const float4* p) {
#pragma unroll
            for (int i = 0; i < 4; i++) {
                int idx = tid + i * 256;
                int row = idx >> 3;
                int kc  = (idx & 7) << 2;
                uint4 t = make_uint4(f2tf(p[i].x), f2tf(p[i].y),
                                     f2tf(p[i].z), f2tf(p[i].w));
                *reinterpret_cast<uint4*>(&As[row * 36 + kc]) = t;
            }
        };
        auto loadB = [&](int kt, float4* p) {
#pragma unroll
            for (int i = 0; i < 4; i++) {
                int idx = tid + i * 256;
                int row = idx >> 3;
                int kc  = (idx & 7) << 2;
                p[i] = *reinterpret_cast<const float4*>(
                    &W1[(size_t)(n0 + row) * K_ + kt * 32 + kc]);
            }
        };
        auto storeB = [&](const float4* p) {
#pragma unroll
            for (int i = 0; i < 4; i++) {
                int idx = tid + i * 256;
                int row = idx >> 3;
                int kc  = (idx & 7) << 2;
                uint4 t = make_uint4(f2tf(p[i].x), f2tf(p[i].y),
                                     f2tf(p[i].z), f2tf(p[i].w));
                *reinterpret_cast<uint4*>(&Bs[row * 36 + kc]) = t;
            }
        };

        loadA(0, pa); loadB(0, pb);
        storeA(pa);   storeB(pb);
        __syncthreads();

        for (int kt = 0; kt < KT; kt++) {
            if (kt + 1 < KT) { loadA(kt + 1, pa); loadB(kt + 1, pb); }
#pragma unroll
            for (int kk = 0; kk < 4; kk++) {
                uint32_t afr[2][4];
#pragma unroll
                for (int mi = 0; mi < 2; mi++) {
                    int r0 = wm * 32 + mi * 16 + (lane >> 2);
                    int kb = kk * 8 + (lane & 3);
                    afr[mi][0] = __float_as_uint(As[r0 * 36 + kb]);
                    afr[mi][1] = __float_as_uint(As[(r0 + 8) * 36 + kb]);
                    afr[mi][2] = __float_as_uint(As[r0 * 36 + kb + 4]);
                    afr[mi][3] = __float_as_uint(As[(r0 + 8) * 36 + kb + 4]);
                }
#pragma unroll
                for (int nj = 0; nj < 8; nj++) {
                    int nn = wn * 64 + nj * 8 + (lane >> 2);
                    int k0 = kk * 8 + (lane & 3);
                    uint32_t b0 = __float_as_uint(Bs[nn * 36 + k0]);
                    uint32_t b1 = __float_as_uint(Bs[nn * 36 + k0 + 4]);
                    mma_tf32(acc[0][nj], afr[0], b0, b1);
                    mma_tf32(acc[1][nj], afr[1], b0, b1);
                }
            }
            __syncthreads();
            if (kt + 1 < KT) {
                storeA(pa); storeB(pb);
                __syncthreads();
            }
        }

        const int lr  = lane >> 2;
        const int lc2 = (lane & 3) * 2;
#pragma unroll
        for (int mi = 0; mi < 2; mi++) {
#pragma unroll
            for (int nj = 0; nj < 8; nj++) {
                int row = m0 + wm * 32 + mi * 16 + lr;
                int col = n0 + wn * 64 + nj * 8 + lc2;
                const float* cc = acc[mi][nj];
#pragma unroll
                for (int half = 0; half < 2; half++) {
                    int rr = row + half * 8;
                    float2 o;
                    o.x = cc[half * 2 + 0] + b1[col];
                    o.y = cc[half * 2 + 1] + b1[col + 1];
                    *reinterpret_cast<float2*>(&h1[(size_t)rr * N_ + col]) = o;
                }
            }
        }
    } else {
        // ---------------- rowsum + adj->fp16 pack ----------------
        uint2 (*sm)[32 * 9] = reinterpret_cast<uint2 (*)[32 * 9]>(dyn);

        const int blk  = blockIdx.x - 128;    // 0..511
        const int M0   = blk * 16;
        const int g    = tid >> 5;            // 0..7
        const int lane = tid & 31;

        const float2* p0 = reinterpret_cast<const float2*>(
            adj + (size_t)(M0 + g) * NN) + lane;
        const float2* p1 = reinterpret_cast<const float2*>(
            adj + (size_t)(M0 + g + 8) * NN) + lane;

        const int sidx = lane * 9 + (g ^ ((lane & 3) << 1));
        const int ridx = (tid >> 3) * 9 + (tid & 7);

        float s0 = 0.f, s1 = 0.f;

        for (int ot = 0; ot < 32; ot++) {
            float2 c0[4], c1[4];
#pragma unroll
            for (int sub = 0; sub < 4; sub++) {
                c0[sub] = p0[(ot * 4 + sub) * 32];
                c1[sub] = p1[(ot * 4 + sub) * 32];
            }
#pragma unroll
            for (int sub = 0; sub < 4; sub++) {
                s0 += c0[sub].x + c0[sub].y;
                s1 += c1[sub].x + c1[sub].y;
                uint2 u;
                u.x = pk16(c0[sub].y, c0[sub].x);
                u.y = pk16(c1[sub].y, c1[sub].x);
                sm[sub][sidx] = u;
            }
            __syncthreads();
#pragma unroll
            for (int sub = 0; sub < 4; sub++)
                Ap[((size_t)blk * 128 + ot * 4 + sub) * 256 + tid] = sm[sub][ridx];
            __syncthreads();
        }

        for (int o = 16; o > 0; o >>= 1) {
            s0 += __shfl_down_sync(0xffffffffu, s0, o);
            s1 += __shfl_down_sync(0xffffffffu, s1, o);
        }
        if (lane == 0) {
            r[M0 + g]     = rsqrtf(s0 + 1.0f);
            r[M0 + g + 8] = rsqrtf(s1 + 1.0f);
        }
    }
}

// ---------------------------------------------------------------------------
// gemm2 (tf32): g = rvec[row] * (h1 @ W2^T + b2)   [8192, 512], K=256
// Epilogue also scatters fp16(g) into fragment-packed Bp:
//   element (k=row, n=col), j=k&15:
//   byte = ((k>>4)*512+n)*32 + (j&7)>>1 *8 + (j>=8 ? 4:0) + (j&1)*2
// ---------------------------------------------------------------------------
__global__ __launch_bounds__(256) void gemm2_tf32(
    const float* __restrict__ A, const float* __restrict__ B, float* __restrict__ C,
    const float* __restrict__ bias, const float* __restrict__ rvec,
    char* __restrict__ BpB) {

    const int M_ = NN, N_ = OUTF, K_ = HID;

    __shared__ __align__(16) float As[128 * 36];
    __shared__ __align__(16) float Bs[128 * 36];

    const int tid  = threadIdx.x;
    const int lane = tid & 31;
    const int warp = tid >> 5;
    const int wm = warp >> 1;
    const int wn = warp & 1;
    const int m0 = blockIdx.y * 128;
    const int n0 = blockIdx.x * 128;
    const int KT = K_ / 32;

    float acc[2][8][4];
#pragma unroll
    for (int mi = 0; mi < 2; mi++)
#pragma unroll
        for (int nj = 0; nj < 8; nj++)
#pragma unroll
            for (int q = 0; q < 4; q++) acc[mi][nj][q] = 0.f;

    float4 pa[4], pb[4];

    auto loadA = [&](int kt, float4* p) {
#pragma unroll
        for (int i = 0; i < 4; i++) {
            int idx = tid + i * 256;
            int row = idx >> 3;
            int kc  = (idx & 7) << 2;
            p[i] = *reinterpret_cast<const float4*>(
                &A[(size_t)(m0 + row) * K_ + kt * 32 + kc]);
        }
    };
    auto storeA = [&](const float4* p) {
#pragma unroll
        for (int i = 0; i < 4; i++) {
            int idx = tid + i * 256;
            int row = idx >> 3;
            int kc  = (idx & 7) << 2;
            uint4 t = make_uint4(f2tf(p[i].x), f2tf(p[i].y), f2tf(p[i].z), f2tf(p[i].w));
            *reinterpret_cast<uint4*>(&As[row * 36 + kc]) = t;
        }
    };
    auto loadB = [&](int kt, float4* p) {
#pragma unroll
        for (int i = 0; i < 4; i++) {
            int idx = tid + i * 256;
            int row = idx >> 3;
            int kc  = (idx & 7) << 2;
            p[i] = *reinterpret_cast<const float4*>(
                &B[(size_t)(n0 + row) * K_ + kt * 32 + kc]);
        }
    };
    auto storeB = [&](const float4* p) {
#pragma unroll
        for (int i = 0; i < 4; i++) {
            int idx = tid + i * 256;
            int row = idx >> 3;
            int kc  = (idx & 7) << 2;
            uint4 t = make_uint4(f2tf(p[i].x), f2tf(p[i].y), f2tf(p[i].z), f2tf(p[i].w));
            *reinterpret_cast<uint4*>(&Bs[row * 36 + kc]) = t;
        }
    };

    loadA(0, pa); loadB(0, pb);
    storeA(pa);   storeB(pb);
    __syncthreads();

    for (int kt = 0; kt < KT; kt++) {
        if (kt + 1 < KT) { loadA(kt + 1, pa); loadB(kt + 1, pb); }

#pragma unroll
        for (int kk = 0; kk < 4; kk++) {
            uint32_t afr[2][4];
#pragma unroll
            for (int mi = 0; mi < 2; mi++) {
                int r0 = wm * 32 + mi * 16 + (lane >> 2);
                int kb = kk * 8 + (lane & 3);
                afr[mi][0] = __float_as_uint(As[r0 * 36 + kb]);
                afr[mi][1] = __float_as_uint(As[(r0 + 8) * 36 + kb]);
                afr[mi][2] = __float_as_uint(As[r0 * 36 + kb + 4]);
                afr[mi][3] = __float_as_uint(As[(r0 + 8) * 36 + kb + 4]);
            }
#pragma unroll
            for (int nj = 0; nj < 8; nj++) {
                int nn = wn * 64 + nj * 8 + (lane >> 2);
                int k0 = kk * 8 + (lane & 3);
                uint32_t b0 = __float_as_uint(Bs[nn * 36 + k0]);
                uint32_t b1 = __float_as_uint(Bs[nn * 36 + k0 + 4]);
                mma_tf32(acc[0][nj], afr[0], b0, b1);
                mma_tf32(acc[1][nj], afr[1], b0, b1);
            }
        }
        __syncthreads();
        if (kt + 1 < KT) {
            storeA(pa); storeB(pb);
            __syncthreads();
        }
    }

    const int lr  = lane >> 2;
    const int lc2 = (lane & 3) * 2;
#pragma unroll
    for (int mi = 0; mi < 2; mi++) {
#pragma unroll
        for (int nj = 0; nj < 8; nj++) {
            int row = m0 + wm * 32 + mi * 16 + lr;
            int col = n0 + wn * 64 + nj * 8 + lc2;
            const float* cc = acc[mi][nj];
#pragma unroll
            for (int half = 0; half < 2; half++) {
                int rr = row + half * 8;
                float rv = rvec[rr];
                float2 o;
                o.x = rv * (cc[half * 2 + 0] + bias[col]);
                o.y = rv * (cc[half * 2 + 1] + bias[col + 1]);
                *reinterpret_cast<float2*>(&C[(size_t)rr * N_ + col]) = o;
                // fused fragment pack (lr = j&7, half selects word0/word1)
                size_t ub = ((size_t)(rr >> 4) * 512 + col) * 32
                          + (size_t)(lr >> 1) * 8 + (half ? 4 : 0) + (lr & 1) * 2;
                *reinterpret_cast<__half*>(BpB + ub)      = __float2half_rn(o.x);
                *reinterpret_cast<__half*>(BpB + ub + 32) = __float2half_rn(o.y);
            }
        }
    }
}

// ---------------------------------------------------------------------------
// GEMM3 (fp16): out = diag(r) * (adj @ g + g)   [8192x512], K=8192
// CTA 128m x 256n, 256 threads, warp grid 2m x 4n (warp tile 64x64),
// ktile 64, 4-stage cp.async pipeline (wait_group 2), 1 sync per ktile.
// ---------------------------------------------------------------------------
#define G3_S   4
#define G3_AB  16384
#define G3_BB  32768
#define G3_SMEM (G3_S * (G3_AB + G3_BB)) // 192 KB
#define G3_KT  (NN / 64)                 // 128

__global__ __launch_bounds__(256, 1) void gemm3_fp16(
    const uint2* __restrict__ Ap, const uint4* __restrict__ Bp,
    const float* __restrict__ g, const float* __restrict__ rvec,
    float* __restrict__ out) {

    extern __shared__ __align__(16) char smem[];
    char* smA = smem;                    // 4 x 16 KB
    char* smB = smem + G3_S * G3_AB;     // 4 x 32 KB

    const int tid  = threadIdx.x;
    const int lane = tid & 31;
    const int wid  = tid >> 5;
    const int wm = wid >> 2;             // 0..1
    const int wn = wid & 3;              // 0..3
    const int m0 = blockIdx.y * 128;
    const int n0 = blockIdx.x * 256;
    const int blk16base = m0 >> 4;

    const char* ApB = reinterpret_cast<const char*>(Ap);
    const char* BpB = reinterpret_cast<const char*>(Bp);

    auto issue = [&](int kt, int slot) {
        uint32_t dA = smem_u32(smA + slot * G3_AB);
        uint32_t dB = smem_u32(smB + slot * G3_BB);
#pragma unroll
        for (int i = 0; i < 4; i++) {
            int task = tid + i * 256;
            int blk = task >> 7;
            int off = task & 127;
            const char* s = ApB + ((size_t)(blk16base + blk) * 128 + kt) * 2048
                          + (size_t)off * 16;
            CP_ASYNC16(dA + task * 16, s);
        }
#pragma unroll
        for (int i = 0; i < 8; i++) {
            int task = tid + i * 256;
            int ks  = task >> 9;
            int off = task & 511;
            const char* s = BpB + ((size_t)(kt * 4 + ks) * 512 + n0) * 32
                          + (size_t)off * 16;
            CP_ASYNC16(dB + task * 16, s);
        }
        CP_COMMIT();
    };

    float acc[4][8][4];
#pragma unroll
    for (int mi = 0; mi < 4; mi++)
#pragma unroll
        for (int nj = 0; nj < 8; nj++)
#pragma unroll
            for (int q = 0; q < 4; q++) acc[mi][nj][q] = 0.f;

    issue(0, 0);
    issue(1, 1);
    issue(2, 2);

    const int g8 = lane >> 2;
    const int t4 = lane & 3;
    const int axor = g8 ^ (t4 << 1);

    for (int kt = 0; kt < G3_KT; kt++) {
        const int slot = kt & (G3_S - 1);
        const int rem = G3_KT - 1 - kt;
        if (rem >= 2)      { CP_WAIT2(); }
        else if (rem == 1) { CP_WAIT1(); }
        else               { CP_WAIT0(); }
        __syncthreads();
        if (kt + G3_S - 1 < G3_KT) issue(kt + G3_S - 1, (kt + G3_S - 1) & (G3_S - 1));

        const char* Ab = smA + slot * G3_AB;
        const char* Bb = smB + slot * G3_BB;

#pragma unroll
        for (int ks = 0; ks < 4; ks++) {
            uint32_t af[4][4];
#pragma unroll
            for (int mi = 0; mi < 4; mi++) {
                int blk = wm * 4 + mi;
                const char* p = Ab
                    + (size_t)(blk * 256 + (ks * 8 + t4) * 8 + axor) * 8;
                uint2 x = *reinterpret_cast<const uint2*>(p);
                uint2 y = *reinterpret_cast<const uint2*>(p + 256);
                af[mi][0] = x.x; af[mi][1] = x.y;
                af[mi][2] = y.x; af[mi][3] = y.y;
            }
            uint32_t bf[8][2];
#pragma unroll
            for (int nj = 0; nj < 8; nj++) {
                const char* p = Bb
                    + (size_t)(((ks * 256 + wn * 64 + nj * 8 + g8) * 4) + t4) * 8;
                uint2 x = *reinterpret_cast<const uint2*>(p);
                bf[nj][0] = x.x; bf[nj][1] = x.y;
            }
#pragma unroll
            for (int mi = 0; mi < 4; mi++)
#pragma unroll
                for (int nj = 0; nj < 8; nj++)
                    mma_fp16(acc[mi][nj], af[mi], bf[nj]);
        }
    }

    // epilogue: out = r * (acc + g)
#pragma unroll
    for (int mi = 0; mi < 4; mi++) {
#pragma unroll
        for (int h = 0; h < 2; h++) {
            int row = m0 + wm * 64 + mi * 16 + g8 + h * 8;
            float rv = rvec[row];
            const float* gp = g + (size_t)row * OUTF;
            float* op = out + (size_t)row * OUTF;
#pragma unroll
            for (int nj = 0; nj < 8; nj++) {
                int col = n0 + wn * 64 + nj * 8 + t4 * 2;
                float2 gv = *reinterpret_cast<const float2*>(gp + col);
                float2 o;
                o.x = rv * (acc[mi][nj][h * 2 + 0] + gv.x);
                o.y = rv * (acc[mi][nj][h * 2 + 1] + gv.y);
                *reinterpret_cast<float2*>(op + col) = o;
            }
        }
    }
}

// ---------------------------------------------------------------------------
extern "C" void kernel_launch(void* const* d_in, const int* in_sizes, int n_in,
                              void* d_out, int out_size) {
    const float* x   = (const float*)d_in[0];
    const float* adj = (const float*)d_in[1];
    const float* W1  = (const float*)d_in[2];
    const float* b1  = (const float*)d_in[3];
    const float* W2  = (const float*)d_in[4];
    const float* b2  = (const float*)d_in[5];
    float* out = (float*)d_out;

    float *h1p, *gp, *rp;
    uint4* Bpp;
    uint2* App;
    cudaGetSymbolAddress((void**)&h1p, g_h1);
    cudaGetSymbolAddress((void**)&gp, g_gbuf);
    cudaGetSymbolAddress((void**)&Bpp, g_Bp);
    cudaGetSymbolAddress((void**)&App, g_Ap);
    cudaGetSymbolAddress((void**)&rp, g_r);

    cudaFuncSetAttribute(fused_pre, cudaFuncAttributeMaxDynamicSharedMemorySize,
                         PRE_SMEM);
    cudaFuncSetAttribute(gemm3_fp16, cudaFuncAttributeMaxDynamicSharedMemorySize,
                         G3_SMEM);

    // rowsum+pack (blocks 128..639)  ||  h1 = x@W1^T+b1 (blocks 0..127)
    fused_pre<<<640, 256, PRE_SMEM>>>(adj, rp, App, x, W1, h1p, b1);
    // g = r ⊙ (h1 @ W2^T + b2)  (fp32) + fused fp16 fragment pack into Bp
    gemm2_tf32<<<dim3(OUTF / 128, NN / 128), 256>>>(
        h1p, W2, gp, b2, rp, (char*)Bpp);
    // out = diag(r) * (adj @ g + g)   (fp16 MMA)
    gemm3_fp16<<<dim3(2, 64), 256, G3_SMEM>>>(App, Bpp, gp, rp, out);
}